// round 10
// baseline (speedup 1.0000x reference)
#include <cuda_runtime.h>
#include <math.h>
#include <stdint.h>

#define B   16
#define T   12
#define NN  2048
#define FI  32
#define FO  64
#define KC  3

// ---------------- static scratch (no allocations allowed) ----------------
__device__ float g_qt[(size_t)B*T*NN];
__device__ float g_kt[(size_t)B*T*NN];
__device__ float g_ta[(size_t)B*T*T];
__device__ __align__(16) float g_xta[(size_t)B*T*NN*FI];
__device__ __align__(16) float g_qs[(size_t)B*NN*T];   // (B,N,T) transposed
__device__ __align__(16) float g_ks[(size_t)B*NN*T];   // (B,N,T) transposed
__device__ __align__(16) float g_sa[(size_t)B*NN*NN];
__device__ __align__(16) float g_xgc[(size_t)B*T*NN*FO];

// pack {hi_half=bf16(h), lo_half=bf16(l)}
__device__ __forceinline__ unsigned bf2(float h, float l) {
    unsigned r;
    asm("cvt.rn.bf16x2.f32 %0, %1, %2;" : "=r"(r) : "f"(h), "f"(l));
    return r;
}
// m16n8k16 bf16 MMA, fp32 accumulate (sm_80+ baseline PTX)
__device__ __forceinline__ void mma_bf16(float* c, const unsigned* a, const unsigned* b) {
    asm volatile(
        "mma.sync.aligned.m16n8k16.row.col.f32.bf16.bf16.f32 "
        "{%0,%1,%2,%3}, {%4,%5,%6,%7}, {%8,%9}, {%0,%1,%2,%3};"
        : "+f"(c[0]), "+f"(c[1]), "+f"(c[2]), "+f"(c[3])
        : "r"(a[0]), "r"(a[1]), "r"(a[2]), "r"(a[3]), "r"(b[0]), "r"(b[1]));
}
__device__ __forceinline__ void ldsm4(unsigned& r0, unsigned& r1, unsigned& r2, unsigned& r3,
                                      uint32_t a) {
    asm volatile("ldmatrix.sync.aligned.m8n8.x4.shared.b16 {%0,%1,%2,%3}, [%4];"
                 : "=r"(r0), "=r"(r1), "=r"(r2), "=r"(r3) : "r"(a));
}
__device__ __forceinline__ uint32_t s2u(const void* p) {
    uint32_t a;
    asm("{ .reg .u64 t; cvta.to.shared.u64 t, %1; cvt.u32.u64 %0, t; }" : "=r"(a) : "l"(p));
    return a;
}
#define SWZ(o) ((o) ^ (((o) >> 3) & 0x70))

// ---------------- K1: qt/kt = x @ wq_t / wk_t ----------------
__global__ void k1_qk(const float* __restrict__ x,
                      const float* __restrict__ wq, const float* __restrict__ wk)
{
    __shared__ float sw[64];
    int tid = threadIdx.x;
    if (tid < 64) sw[tid] = (tid < 32) ? wq[tid] : wk[tid - 32];
    __syncthreads();
    size_t g = (size_t)blockIdx.x * 256 + tid;
    const float4* xr = (const float4*)(x + g * FI);
    float aq = 0.f, ak = 0.f;
#pragma unroll
    for (int u = 0; u < 8; u++) {
        float4 v = xr[u];
        aq += v.x*sw[u*4+0] + v.y*sw[u*4+1] + v.z*sw[u*4+2] + v.w*sw[u*4+3];
        ak += v.x*sw[32+u*4+0] + v.y*sw[32+u*4+1] + v.z*sw[32+u*4+2] + v.w*sw[32+u*4+3];
    }
    g_qt[g] = aq; g_kt[g] = ak;
}

// ---------------- K2: temporal attention ----------------
__global__ void k2_ta()
{
    int b = blockIdx.x / T, t = blockIdx.x % T;
    int tid = threadIdx.x;
    const float* q  = g_qt + ((size_t)b*T + t) * NN;
    const float* kb = g_kt + (size_t)b*T*NN;
    float p[T];
#pragma unroll
    for (int s = 0; s < T; s++) p[s] = 0.f;
    for (int n = tid; n < NN; n += 256) {
        float qv = q[n];
#pragma unroll
        for (int s = 0; s < T; s++) p[s] += qv * kb[(size_t)s*NN + n];
    }
    __shared__ float sc[T];
    if (tid < T) sc[tid] = 0.f;
    __syncthreads();
#pragma unroll
    for (int s = 0; s < T; s++) {
        float v = p[s];
        for (int off = 16; off; off >>= 1) v += __shfl_down_sync(0xffffffffu, v, off);
        if ((tid & 31) == 0) atomicAdd(&sc[s], v);
    }
    __syncthreads();
    if (tid == 0) {
        const float isN = 0.022097086912079612f;
        float sv[T], mx = -1e30f;
#pragma unroll
        for (int s = 0; s < T; s++) { sv[s] = sc[s]*isN; mx = fmaxf(mx, sv[s]); }
        float sum = 0.f;
#pragma unroll
        for (int s = 0; s < T; s++) { sv[s] = __expf(sv[s]-mx); sum += sv[s]; }
        float inv = 1.f / sum;
        float* out = g_ta + ((size_t)b*T + t) * T;
#pragma unroll
        for (int s = 0; s < T; s++) out[s] = sv[s]*inv;
    }
}

// ---------------- K3: x_ta ----------------
__global__ __launch_bounds__(1024) void k3_xta(const float* __restrict__ x)
{
    __shared__ float tas[T*T];
    int b = blockIdx.y, n0 = blockIdx.x << 5;
    int tid = threadIdx.x;
    if (tid < T*T) tas[tid] = g_ta[(size_t)b*T*T + tid];
    __syncthreads();
    int f = tid & 31, nl = tid >> 5;
    size_t base = ((size_t)b*T*NN + (n0 + nl)) * FI + f;
    float v[T];
#pragma unroll
    for (int s = 0; s < T; s++) v[s] = x[base + (size_t)s*NN*FI];
#pragma unroll
    for (int t = 0; t < T; t++) {
        float a = 0.f;
#pragma unroll
        for (int s = 0; s < T; s++) a += tas[t*T + s] * v[s];
        g_xta[base + (size_t)t*NN*FI] = a;
    }
}

// ---------------- K4: qs/ks ----------------
__global__ void k4_qk(const float* __restrict__ wq, const float* __restrict__ wk)
{
    __shared__ float sw[64];
    int tid = threadIdx.x;
    if (tid < 64) sw[tid] = (tid < 32) ? wq[tid] : wk[tid - 32];
    __syncthreads();
    size_t g = (size_t)blockIdx.x * 256 + tid;
    const float4* xr = (const float4*)(g_xta + g * FI);
    float aq = 0.f, ak = 0.f;
#pragma unroll
    for (int u = 0; u < 8; u++) {
        float4 v = xr[u];
        aq += v.x*sw[u*4+0] + v.y*sw[u*4+1] + v.z*sw[u*4+2] + v.w*sw[u*4+3];
        ak += v.x*sw[32+u*4+0] + v.y*sw[32+u*4+1] + v.z*sw[32+u*4+2] + v.w*sw[32+u*4+3];
    }
    int n = (int)(g % NN);
    size_t bt = g / NN;
    int t = (int)(bt % T);
    int b = (int)(bt / T);
    size_t o = ((size_t)b*NN + n) * T + t;
    g_qs[o] = aq; g_ks[o] = ak;
}

// ---------------- K5: spatial attention ----------------
__global__ __launch_bounds__(256) void k5_sa()
{
    __shared__ float buf[NN];
    __shared__ float red[256];
    __shared__ float qr[T];
    int b = blockIdx.x >> 11;
    int i = blockIdx.x & (NN - 1);
    int tid = threadIdx.x;
    const float* qsb = g_qs + ((size_t)b*NN + i) * T;
    const float* ksb = g_ks + (size_t)b*NN*T;
    if (tid < T) qr[tid] = qsb[tid];
    __syncthreads();
    const float isT = 0.28867513459481287f;
    float lmax = -1e30f;
    for (int m = tid; m < NN; m += 256) {
        const float4* kr = (const float4*)(ksb + (size_t)m * T);
        float4 A = kr[0], Bv = kr[1], C = kr[2];
        float s = qr[0]*A.x + qr[1]*A.y + qr[2]*A.z + qr[3]*A.w
                + qr[4]*Bv.x + qr[5]*Bv.y + qr[6]*Bv.z + qr[7]*Bv.w
                + qr[8]*C.x + qr[9]*C.y + qr[10]*C.z + qr[11]*C.w;
        s *= isT;
        buf[m] = s;
        lmax = fmaxf(lmax, s);
    }
    red[tid] = lmax; __syncthreads();
    for (int s = 128; s > 0; s >>= 1) { if (tid < s) red[tid] = fmaxf(red[tid], red[tid+s]); __syncthreads(); }
    float mx = red[0]; __syncthreads();
    float lsum = 0.f;
    for (int m = tid; m < NN; m += 256) { float e = __expf(buf[m]-mx); buf[m] = e; lsum += e; }
    red[tid] = lsum; __syncthreads();
    for (int s = 128; s > 0; s >>= 1) { if (tid < s) red[tid] += red[tid+s]; __syncthreads(); }
    float inv = 1.f / red[0];
    float* out = g_sa + ((size_t)b*NN + i) * NN;
    for (int m = tid; m < NN; m += 256) out[m] = buf[m] * inv;
}

// ---------------- K6: warp-MMA bf16-split Chebyshev GEMM + theta epilogue ----------------
// 512 threads, 16 warps in 4(m) x 4(n) grid; warp tile 32m x 16n; ldmatrix fragment loads.
// D_k = Ah@Bh + Ah@Bl + Al@Bh in fp32 acc (err ~2^-18).
#define K6_BK     64
#define K6_ITERS  (NN / K6_BK)     // 32
// smem byte offsets (tiles SW128-swizzled, bf16, 128B rows)
#define OFF_AH(k)  ((k)*32768)
#define OFF_AL(k)  ((k)*32768 + 16384)
#define OFF_BH     98304
#define OFF_BL     106496
// epilogue overlay (floats)
#define CS_STR     68
#define CS_K       (128*CS_STR)            // 8704 floats per k
#define THS_OFF    (3*CS_K)                // 26112 floats
#define K6_SMEM    ((THS_OFF + KC*FI*FO) * 4)   // 129024 bytes

__global__ __launch_bounds__(512, 1)
void k6_mma(const float* __restrict__ cheb, const float* __restrict__ theta)
{
    extern __shared__ __align__(1024) char smem[];
    const int b  = blockIdx.z;
    const int i0 = blockIdx.y * 128;
    const int t0 = blockIdx.x * 2;
    const int tid = threadIdx.x, wid = tid >> 5, lane = tid & 31;
    const int g = lane >> 2, q = lane & 3;
    const int wm = wid & 3, wn = wid >> 2;
    const uint32_t sb = s2u(smem);

    const float* sab = g_sa  + (size_t)b * NN * NN;
    const float* xb  = g_xta + (size_t)b * T * NN * FI;

    // ldmatrix per-lane base byte offsets (within a tile)
    const uint32_t aRow0 = (uint32_t)((wm*32 + ((lane >> 3) & 1)*8 + (lane & 7)) * 128
                                      + (lane >> 4) * 16);
    const uint32_t aRow1 = aRow0 + 16*128;
    const uint32_t bRow  = (uint32_t)((wn*16 + ((lane >> 4) & 1)*8 + (lane & 7)) * 128
                                      + ((lane >> 3) & 1) * 16);

    float acc[3][2][2][4];
#pragma unroll
    for (int k = 0; k < 3; k++)
#pragma unroll
        for (int mt = 0; mt < 2; mt++)
#pragma unroll
            for (int nt = 0; nt < 2; nt++)
#pragma unroll
                for (int c = 0; c < 4; c++) acc[k][mt][nt][c] = 0.f;

    for (int iter = 0; iter < K6_ITERS; iter++) {
        const int j0 = iter * K6_BK;
        if (iter > 0) __syncthreads();    // prev compute done before overwrite

        // ---- produce A tiles: rows of (cheb_k * sa), bf16 hi/lo, SW128 K-major ----
#pragma unroll
        for (int p = 0; p < 2; p++) {
            int ii = p*64 + wid*4 + (lane >> 3);     // 0..127
            int jq = lane & 7;                        // 8-elem chunk
            size_t go = (size_t)(i0 + ii) * NN + j0 + jq*8;
            float4 s0 = *(const float4*)(sab + go);
            float4 s1 = *(const float4*)(sab + go + 4);
            uint32_t sw = SWZ((uint32_t)(ii*128 + jq*16));
#pragma unroll
            for (int k = 0; k < 3; k++) {
                const float* cb = cheb + (size_t)k*NN*NN + go;
                float4 c0 = *(const float4*)(cb);
                float4 c1 = *(const float4*)(cb + 4);
                float a0 = c0.x*s0.x, a1 = c0.y*s0.y, a2 = c0.z*s0.z, a3 = c0.w*s0.w;
                float a4 = c1.x*s1.x, a5 = c1.y*s1.y, a6 = c1.z*s1.z, a7 = c1.w*s1.w;
                uint4 hv;
                hv.x = bf2(a1, a0); hv.y = bf2(a3, a2); hv.z = bf2(a5, a4); hv.w = bf2(a7, a6);
                float h0 = __uint_as_float(hv.x << 16), h1 = __uint_as_float(hv.x & 0xFFFF0000u);
                float h2 = __uint_as_float(hv.y << 16), h3 = __uint_as_float(hv.y & 0xFFFF0000u);
                float h4 = __uint_as_float(hv.z << 16), h5 = __uint_as_float(hv.z & 0xFFFF0000u);
                float h6 = __uint_as_float(hv.w << 16), h7 = __uint_as_float(hv.w & 0xFFFF0000u);
                uint4 lv;
                lv.x = bf2(a1 - h1, a0 - h0); lv.y = bf2(a3 - h3, a2 - h2);
                lv.z = bf2(a5 - h5, a4 - h4); lv.w = bf2(a7 - h7, a6 - h6);
                *(uint4*)(smem + OFF_AH(k) + sw) = hv;
                *(uint4*)(smem + OFF_AL(k) + sw) = lv;
            }
        }
        // ---- produce B tiles: B[n][j] = x_ta[t0 + n/32][j][n%32], hi/lo ----
#pragma unroll
        for (int pass = 0; pass < 4; pass++) {
            int n = pass*16 + wid;                  // 0..63
            int t = t0 + (n >> 5), f = n & 31;
            const float* src = xb + ((size_t)t*NN + (j0 + 2*lane)) * FI + f;
            float x0 = src[0], x1 = src[FI];
            unsigned hi2 = bf2(x1, x0);
            float h0 = __uint_as_float(hi2 << 16), h1 = __uint_as_float(hi2 & 0xFFFF0000u);
            unsigned lo2 = bf2(x1 - h1, x0 - h0);
            uint32_t sw = SWZ((uint32_t)(n*128 + lane*4));
            *(unsigned*)(smem + OFF_BH + sw) = hi2;
            *(unsigned*)(smem + OFF_BL + sw) = lo2;
        }
        __syncthreads();

        // ---- compute: ldmatrix + mma over 4 K=16 steps ----
#pragma unroll
        for (int kk = 0; kk < 4; kk++) {
            const uint32_t kb = (uint32_t)kk * 32;
            unsigned bh[4], bl[4];
            ldsm4(bh[0], bh[1], bh[2], bh[3], sb + OFF_BH + SWZ(bRow + kb));
            ldsm4(bl[0], bl[1], bl[2], bl[3], sb + OFF_BL + SWZ(bRow + kb));
#pragma unroll
            for (int k = 0; k < 3; k++) {
                unsigned a0[4], a1[4];
                ldsm4(a0[0], a0[1], a0[2], a0[3], sb + OFF_AH(k) + SWZ(aRow0 + kb));
                ldsm4(a1[0], a1[1], a1[2], a1[3], sb + OFF_AH(k) + SWZ(aRow1 + kb));
                mma_bf16(acc[k][0][0], a0, bh + 0); mma_bf16(acc[k][0][1], a0, bh + 2);
                mma_bf16(acc[k][1][0], a1, bh + 0); mma_bf16(acc[k][1][1], a1, bh + 2);
                mma_bf16(acc[k][0][0], a0, bl + 0); mma_bf16(acc[k][0][1], a0, bl + 2);
                mma_bf16(acc[k][1][0], a1, bl + 0); mma_bf16(acc[k][1][1], a1, bl + 2);
                ldsm4(a0[0], a0[1], a0[2], a0[3], sb + OFF_AL(k) + SWZ(aRow0 + kb));
                ldsm4(a1[0], a1[1], a1[2], a1[3], sb + OFF_AL(k) + SWZ(aRow1 + kb));
                mma_bf16(acc[k][0][0], a0, bh + 0); mma_bf16(acc[k][0][1], a0, bh + 2);
                mma_bf16(acc[k][1][0], a1, bh + 0); mma_bf16(acc[k][1][1], a1, bh + 2);
            }
        }
    }
    __syncthreads();

    // ---- stage accumulators to smem (overlay A region) ----
    float* Cs = (float*)smem;
#pragma unroll
    for (int k = 0; k < 3; k++)
#pragma unroll
        for (int mt = 0; mt < 2; mt++)
#pragma unroll
            for (int nt = 0; nt < 2; nt++) {
                int row = wm*32 + mt*16 + g;
                int col = wn*16 + nt*8 + q*2;
                float2 v0 = make_float2(acc[k][mt][nt][0], acc[k][mt][nt][1]);
                float2 v1 = make_float2(acc[k][mt][nt][2], acc[k][mt][nt][3]);
                *(float2*)(Cs + k*CS_K + row*CS_STR + col) = v0;
                *(float2*)(Cs + k*CS_K + (row + 8)*CS_STR + col) = v1;
            }
    // theta into smem (overlay B region)
    float* ths = Cs + THS_OFF;                 // [3][32][64]
    for (int idx = tid; idx < KC*FI*FO; idx += 512) ths[idx] = theta[idx];
    __syncthreads();

    // ---- epilogue: out[i][tt][o] = relu( sum_k sum_f D_k[i][tt*32+f]*th[k][f][o] ) ----
    {
        const int i = tid >> 2, seg = tid & 3, o0 = seg*16;
        float out0[16], out1[16];
#pragma unroll
        for (int o = 0; o < 16; o++) { out0[o] = 0.f; out1[o] = 0.f; }
#pragma unroll
        for (int k = 0; k < 3; k++) {
            const float* cr = Cs + k*CS_K + i*CS_STR;
#pragma unroll
            for (int f4 = 0; f4 < 8; f4++) {
                float4 c0 = *(const float4*)(cr + f4*4);
                float4 c1 = *(const float4*)(cr + 32 + f4*4);
                const float* cf0 = (const float*)&c0;
                const float* cf1 = (const float*)&c1;
#pragma unroll
                for (int j = 0; j < 4; j++) {
                    float v0 = cf0[j], v1 = cf1[j];
                    const float* th = ths + (k*32 + f4*4 + j)*64 + o0;
#pragma unroll
                    for (int oq = 0; oq < 4; oq++) {
                        float4 t4 = *(const float4*)(th + oq*4);
                        out0[oq*4+0] += v0*t4.x; out0[oq*4+1] += v0*t4.y;
                        out0[oq*4+2] += v0*t4.z; out0[oq*4+3] += v0*t4.w;
                        out1[oq*4+0] += v1*t4.x; out1[oq*4+1] += v1*t4.y;
                        out1[oq*4+2] += v1*t4.z; out1[oq*4+3] += v1*t4.w;
                    }
                }
            }
        }
        size_t base0 = (((size_t)b*T + t0    )*NN + i0 + i)*FO + o0;
        size_t base1 = (((size_t)b*T + t0 + 1)*NN + i0 + i)*FO + o0;
#pragma unroll
        for (int oq = 0; oq < 4; oq++) {
            float4 v0, v1;
            v0.x = fmaxf(out0[oq*4+0], 0.f); v0.y = fmaxf(out0[oq*4+1], 0.f);
            v0.z = fmaxf(out0[oq*4+2], 0.f); v0.w = fmaxf(out0[oq*4+3], 0.f);
            v1.x = fmaxf(out1[oq*4+0], 0.f); v1.y = fmaxf(out1[oq*4+1], 0.f);
            v1.z = fmaxf(out1[oq*4+2], 0.f); v1.w = fmaxf(out1[oq*4+3], 0.f);
            *(float4*)(g_xgc + base0 + oq*4) = v0;
            *(float4*)(g_xgc + base1 + oq*4) = v1;
        }
    }
}

// ---------------- K7: temporal conv + residual conv + relu + layernorm ----------------
#define S7_WS   0
#define S7_XG   15232
#define S7_XR   (S7_XG + 6144)
#define S7_YB   (S7_XR + 1024)
#define S7_MU   (S7_YB + 2080)
#define S7_RI   (S7_MU + 32)
#define S7_TOTF (S7_RI + 32)

__global__ __launch_bounds__(256) void k7_final(
    const float* __restrict__ x,
    const float* __restrict__ tw, const float* __restrict__ tb,
    const float* __restrict__ rw, const float* __restrict__ rb,
    const float* __restrict__ lg, const float* __restrict__ lb,
    float* __restrict__ out)
{
    extern __shared__ float s7[];
    float* Ws = s7 + S7_WS;
    float* xg = s7 + S7_XG;
    float* xr = s7 + S7_XR;
    float* yb = s7 + S7_YB;
    float* mu = s7 + S7_MU;
    float* ri = s7 + S7_RI;

    int b = blockIdx.z, t = blockIdx.y, n0 = blockIdx.x << 5;
    int tid = threadIdx.x;

    for (int idx = tid; idx < FO*192; idx += 256) { int o = idx / 192, r = idx - o*192; Ws[r*68 + o] = tw[idx]; }
    for (int idx = tid; idx < FO*FI; idx += 256) { int o = idx >> 5, f = idx & 31; Ws[(192+f)*68 + o] = rw[idx]; }
#pragma unroll
    for (int dt = 0; dt < 3; dt++) {
        int ts = t + dt - 1;
        if (ts >= 0 && ts < T) {
            const float* src = g_xgc + (((size_t)b*T + ts)*NN + n0) * FO;
            for (int idx = tid; idx < 32*FO; idx += 256) xg[dt*2048 + idx] = src[idx];
        } else {
            for (int idx = tid; idx < 32*FO; idx += 256) xg[dt*2048 + idx] = 0.f;
        }
    }
    {
        const float* src = x + (((size_t)b*T + t)*NN + n0) * FI;
        for (int idx = tid; idx < 32*FI; idx += 256) xr[idx] = src[idx];
    }
    __syncthreads();

    int og = tid & 15, nlg = tid >> 4;
    int o0 = og << 2, nl0 = nlg << 1;
    float4 tb4 = *(const float4*)(tb + o0);
    float4 rb4 = *(const float4*)(rb + o0);
    float acc0[4], acc1[4];
#pragma unroll
    for (int c = 0; c < 4; c++) {
        float bia = ((const float*)&tb4)[c] + ((const float*)&rb4)[c];
        acc0[c] = bia; acc1[c] = bia;
    }

    for (int c = 0; c < FO; c++) {
#pragma unroll
        for (int dt = 0; dt < 3; dt++) {
            float4 w = *(const float4*)(Ws + (c*3 + dt)*68 + o0);
            float xa = xg[dt*2048 + nl0*FO + c];
            float xb2 = xg[dt*2048 + nl0*FO + FO + c];
            acc0[0] += xa*w.x;  acc0[1] += xa*w.y;  acc0[2] += xa*w.z;  acc0[3] += xa*w.w;
            acc1[0] += xb2*w.x; acc1[1] += xb2*w.y; acc1[2] += xb2*w.z; acc1[3] += xb2*w.w;
        }
    }
#pragma unroll
    for (int f = 0; f < FI; f++) {
        float4 w = *(const float4*)(Ws + (192 + f)*68 + o0);
        float xa = xr[nl0*FI + f];
        float xb2 = xr[nl0*FI + FI + f];
        acc0[0] += xa*w.x;  acc0[1] += xa*w.y;  acc0[2] += xa*w.z;  acc0[3] += xa*w.w;
        acc1[0] += xb2*w.x; acc1[1] += xb2*w.y; acc1[2] += xb2*w.z; acc1[3] += xb2*w.w;
    }
#pragma unroll
    for (int c = 0; c < 4; c++) {
        float v0 = acc0[c] > 0.f ? acc0[c] : 0.f;
        float v1 = acc1[c] > 0.f ? acc1[c] : 0.f;
        yb[nl0*65 + o0 + c] = v0;
        yb[(nl0+1)*65 + o0 + c] = v1;
    }
    __syncthreads();
    if (tid < 32) {
        float m = 0.f;
#pragma unroll
        for (int o = 0; o < FO; o++) m += yb[tid*65 + o];
        m *= (1.f/FO);
        float v = 0.f;
#pragma unroll
        for (int o = 0; o < FO; o++) { float d = yb[tid*65 + o] - m; v += d*d; }
        v *= (1.f/FO);
        mu[tid] = m;
        ri[tid] = rsqrtf(v + 1e-5f);
    }
    __syncthreads();
    float4 g4 = *(const float4*)(lg + o0);
    float4 b4 = *(const float4*)(lb + o0);
#pragma unroll
    for (int j = 0; j < 2; j++) {
        int nl = nl0 + j;
        float m = mu[nl], r = ri[nl];
        float4 ov;
        ov.x = (yb[nl*65 + o0 + 0] - m)*r*g4.x + b4.x;
        ov.y = (yb[nl*65 + o0 + 1] - m)*r*g4.y + b4.y;
        ov.z = (yb[nl*65 + o0 + 2] - m)*r*g4.z + b4.z;
        ov.w = (yb[nl*65 + o0 + 3] - m)*r*g4.w + b4.w;
        *(float4*)(out + ((((size_t)b*T + t)*NN + n0 + nl) << 6) + o0) = ov;
    }
}

// ---------------- launch ----------------
extern "C" void kernel_launch(void* const* d_in, const int* in_sizes, int n_in,
                              void* d_out, int out_size)
{
    const float* x     = (const float*)d_in[0];
    const float* cheb  = (const float*)d_in[1];
    const float* wq_t  = (const float*)d_in[2];
    const float* wk_t  = (const float*)d_in[3];
    const float* wq_s  = (const float*)d_in[4];
    const float* wk_s  = (const float*)d_in[5];
    const float* theta = (const float*)d_in[6];
    const float* tw    = (const float*)d_in[7];
    const float* tbv   = (const float*)d_in[8];
    const float* rw    = (const float*)d_in[9];
    const float* rbv   = (const float*)d_in[10];
    const float* lg    = (const float*)d_in[11];
    const float* lb    = (const float*)d_in[12];
    float* out = (float*)d_out;

    cudaFuncSetAttribute(k6_mma, cudaFuncAttributeMaxDynamicSharedMemorySize, K6_SMEM);
    cudaFuncSetAttribute(k7_final, cudaFuncAttributeMaxDynamicSharedMemorySize,
                         S7_TOTF * (int)sizeof(float));

    k1_qk<<<(B*T*NN)/256, 256>>>(x, wq_t, wk_t);
    k2_ta<<<B*T, 256>>>();
    k3_xta<<<dim3(NN/32, B), 1024>>>(x);
    k4_qk<<<(B*T*NN)/256, 256>>>(wq_s, wk_s);
    k5_sa<<<B*NN, 256>>>();
    k6_mma<<<dim3(T/2, NN/128, B), 512, K6_SMEM>>>(cheb, theta);
    k7_final<<<dim3(NN/32, T, B), 256, S7_TOTF * (int)sizeof(float)>>>(
        x, tw, tbv, rw, rbv, lg, lb, out);
}

// round 12
// speedup vs baseline: 1.4523x; 1.4523x over previous
#include <cuda_runtime.h>
#include <math.h>
#include <stdint.h>

#define B   16
#define T   12
#define NN  2048
#define FI  32
#define FO  64
#define KC  3

// ---------------- static scratch (no allocations allowed) ----------------
__device__ float g_qt[(size_t)B*T*NN];
__device__ float g_kt[(size_t)B*T*NN];
__device__ float g_ta[(size_t)B*T*T];
__device__ __align__(16) float g_xta[(size_t)B*T*NN*FI];
__device__ __align__(16) float g_qs[(size_t)B*NN*T];
__device__ __align__(16) float g_ks[(size_t)B*NN*T];
__device__ __align__(16) float g_xgc[(size_t)B*T*NN*FO];
// pre-split A = cheb_k * sa : bf16 hi/lo, [k][b][i][j]
__device__ __align__(16) unsigned short g_ah[(size_t)KC*B*NN*NN];
__device__ __align__(16) unsigned short g_al[(size_t)KC*B*NN*NN];
// pre-split x_ta transposed: [b][t*32+f][n]
__device__ __align__(16) unsigned short g_xbh[(size_t)B*T*FI*NN];
__device__ __align__(16) unsigned short g_xbl[(size_t)B*T*FI*NN];

__device__ __forceinline__ unsigned bf2(float h, float l) {
    unsigned r;
    asm("cvt.rn.bf16x2.f32 %0, %1, %2;" : "=r"(r) : "f"(h), "f"(l));
    return r;
}
__device__ __forceinline__ void mma_bf16(float* c, const unsigned* a, const unsigned* b) {
    asm volatile(
        "mma.sync.aligned.m16n8k16.row.col.f32.bf16.bf16.f32 "
        "{%0,%1,%2,%3}, {%4,%5,%6,%7}, {%8,%9}, {%0,%1,%2,%3};"
        : "+f"(c[0]), "+f"(c[1]), "+f"(c[2]), "+f"(c[3])
        : "r"(a[0]), "r"(a[1]), "r"(a[2]), "r"(a[3]), "r"(b[0]), "r"(b[1]));
}
__device__ __forceinline__ void ldsm4(unsigned& r0, unsigned& r1, unsigned& r2, unsigned& r3,
                                      uint32_t a) {
    asm volatile("ldmatrix.sync.aligned.m8n8.x4.shared.b16 {%0,%1,%2,%3}, [%4];"
                 : "=r"(r0), "=r"(r1), "=r"(r2), "=r"(r3) : "r"(a));
}
__device__ __forceinline__ uint32_t s2u(const void* p) {
    uint32_t a;
    asm("{ .reg .u64 t; cvta.to.shared.u64 t, %1; cvt.u32.u64 %0, t; }" : "=r"(a) : "l"(p));
    return a;
}
__device__ __forceinline__ void cp16(uint32_t dst, const void* src) {
    asm volatile("cp.async.cg.shared.global [%0], [%1], 16;" :: "r"(dst), "l"(src));
}
#define CP_COMMIT() asm volatile("cp.async.commit_group;" ::: "memory")
#define SWZ(o) ((o) ^ (((o) >> 3) & 0x70))

// ---------------- K1 ----------------
__global__ void k1_qk(const float* __restrict__ x,
                      const float* __restrict__ wq, const float* __restrict__ wk)
{
    __shared__ float sw[64];
    int tid = threadIdx.x;
    if (tid < 64) sw[tid] = (tid < 32) ? wq[tid] : wk[tid - 32];
    __syncthreads();
    size_t g = (size_t)blockIdx.x * 256 + tid;
    const float4* xr = (const float4*)(x + g * FI);
    float aq = 0.f, ak = 0.f;
#pragma unroll
    for (int u = 0; u < 8; u++) {
        float4 v = xr[u];
        aq += v.x*sw[u*4+0] + v.y*sw[u*4+1] + v.z*sw[u*4+2] + v.w*sw[u*4+3];
        ak += v.x*sw[32+u*4+0] + v.y*sw[32+u*4+1] + v.z*sw[32+u*4+2] + v.w*sw[32+u*4+3];
    }
    g_qt[g] = aq; g_kt[g] = ak;
}

// ---------------- K2 ----------------
__global__ void k2_ta()
{
    int b = blockIdx.x / T, t = blockIdx.x % T;
    int tid = threadIdx.x;
    const float* q  = g_qt + ((size_t)b*T + t) * NN;
    const float* kb = g_kt + (size_t)b*T*NN;
    float p[T];
#pragma unroll
    for (int s = 0; s < T; s++) p[s] = 0.f;
    for (int n = tid; n < NN; n += 256) {
        float qv = q[n];
#pragma unroll
        for (int s = 0; s < T; s++) p[s] += qv * kb[(size_t)s*NN + n];
    }
    __shared__ float sc[T];
    if (tid < T) sc[tid] = 0.f;
    __syncthreads();
#pragma unroll
    for (int s = 0; s < T; s++) {
        float v = p[s];
        for (int off = 16; off; off >>= 1) v += __shfl_down_sync(0xffffffffu, v, off);
        if ((tid & 31) == 0) atomicAdd(&sc[s], v);
    }
    __syncthreads();
    if (tid == 0) {
        const float isN = 0.022097086912079612f;
        float sv[T], mx = -1e30f;
#pragma unroll
        for (int s = 0; s < T; s++) { sv[s] = sc[s]*isN; mx = fmaxf(mx, sv[s]); }
        float sum = 0.f;
#pragma unroll
        for (int s = 0; s < T; s++) { sv[s] = __expf(sv[s]-mx); sum += sv[s]; }
        float inv = 1.f / sum;
        float* out = g_ta + ((size_t)b*T + t) * T;
#pragma unroll
        for (int s = 0; s < T; s++) out[s] = sv[s]*inv;
    }
}

// ---------------- K3 ----------------
__global__ __launch_bounds__(1024) void k3_xta(const float* __restrict__ x)
{
    __shared__ float tas[T*T];
    int b = blockIdx.y, n0 = blockIdx.x << 5;
    int tid = threadIdx.x;
    if (tid < T*T) tas[tid] = g_ta[(size_t)b*T*T + tid];
    __syncthreads();
    int f = tid & 31, nl = tid >> 5;
    size_t base = ((size_t)b*T*NN + (n0 + nl)) * FI + f;
    float v[T];
#pragma unroll
    for (int s = 0; s < T; s++) v[s] = x[base + (size_t)s*NN*FI];
#pragma unroll
    for (int t = 0; t < T; t++) {
        float a = 0.f;
#pragma unroll
        for (int s = 0; s < T; s++) a += tas[t*T + s] * v[s];
        g_xta[base + (size_t)t*NN*FI] = a;
    }
}

// ---------------- K3b: x_ta -> bf16 hi/lo, transposed [b][t*32+f][n] ----------------
__global__ __launch_bounds__(256) void k3b_cvt()
{
    __shared__ unsigned short sh[32][36];
    __shared__ unsigned short sl[32][36];
    int b = blockIdx.z, t = blockIdx.y, n0 = blockIdx.x << 5;
    int tid = threadIdx.x;
    int n_l = tid >> 3, fq = tid & 7;
    float4 v = *(const float4*)(g_xta + (((size_t)b*T + t)*NN + n0 + n_l)*FI + fq*4);
    const float* vf = (const float*)&v;
#pragma unroll
    for (int j = 0; j < 4; j++) {
        float xv = vf[j];
        unsigned h2 = bf2(0.f, xv);
        float hf = __uint_as_float(h2 << 16);
        unsigned l2 = bf2(0.f, xv - hf);
        sh[fq*4 + j][n_l] = (unsigned short)(h2 & 0xFFFF);
        sl[fq*4 + j][n_l] = (unsigned short)(l2 & 0xFFFF);
    }
    __syncthreads();
    int f = tid >> 3, nq = tid & 7;
    size_t o = ((size_t)b*(T*FI) + t*32 + f)*NN + n0 + nq*4;
    uint2 hp = make_uint2((unsigned)sh[f][nq*4+0] | ((unsigned)sh[f][nq*4+1] << 16),
                          (unsigned)sh[f][nq*4+2] | ((unsigned)sh[f][nq*4+3] << 16));
    uint2 lp = make_uint2((unsigned)sl[f][nq*4+0] | ((unsigned)sl[f][nq*4+1] << 16),
                          (unsigned)sl[f][nq*4+2] | ((unsigned)sl[f][nq*4+3] << 16));
    *(uint2*)(g_xbh + o) = hp;
    *(uint2*)(g_xbl + o) = lp;
}

// ---------------- K4 ----------------
__global__ void k4_qk(const float* __restrict__ wq, const float* __restrict__ wk)
{
    __shared__ float sw[64];
    int tid = threadIdx.x;
    if (tid < 64) sw[tid] = (tid < 32) ? wq[tid] : wk[tid - 32];
    __syncthreads();
    size_t g = (size_t)blockIdx.x * 256 + tid;
    const float4* xr = (const float4*)(g_xta + g * FI);
    float aq = 0.f, ak = 0.f;
#pragma unroll
    for (int u = 0; u < 8; u++) {
        float4 v = xr[u];
        aq += v.x*sw[u*4+0] + v.y*sw[u*4+1] + v.z*sw[u*4+2] + v.w*sw[u*4+3];
        ak += v.x*sw[32+u*4+0] + v.y*sw[32+u*4+1] + v.z*sw[32+u*4+2] + v.w*sw[32+u*4+3];
    }
    int n = (int)(g % NN);
    size_t bt = g / NN;
    int t = (int)(bt % T);
    int b = (int)(bt / T);
    size_t o = ((size_t)b*NN + n) * T + t;
    g_qs[o] = aq; g_ks[o] = ak;
}

// ---------------- K5: spatial attention, fused cheb-mul + bf16 split store ----------------
__global__ __launch_bounds__(256) void k5_sa(const float* __restrict__ cheb)
{
    __shared__ float buf[NN];
    __shared__ float red[256];
    __shared__ float qr[T];
    int b = blockIdx.x >> 11;
    int i = blockIdx.x & (NN - 1);
    int tid = threadIdx.x;
    const float* qsb = g_qs + ((size_t)b*NN + i) * T;
    const float* ksb = g_ks + (size_t)b*NN*T;
    if (tid < T) qr[tid] = qsb[tid];
    __syncthreads();
    const float isT = 0.28867513459481287f;
    float lmax = -1e30f;
    for (int m = tid; m < NN; m += 256) {
        const float4* kr = (const float4*)(ksb + (size_t)m * T);
        float4 A = kr[0], Bv = kr[1], C = kr[2];
        float s = qr[0]*A.x + qr[1]*A.y + qr[2]*A.z + qr[3]*A.w
                + qr[4]*Bv.x + qr[5]*Bv.y + qr[6]*Bv.z + qr[7]*Bv.w
                + qr[8]*C.x + qr[9]*C.y + qr[10]*C.z + qr[11]*C.w;
        s *= isT;
        buf[m] = s;
        lmax = fmaxf(lmax, s);
    }
    red[tid] = lmax; __syncthreads();
    for (int s = 128; s > 0; s >>= 1) { if (tid < s) red[tid] = fmaxf(red[tid], red[tid+s]); __syncthreads(); }
    float mx = red[0]; __syncthreads();
    float lsum = 0.f;
    for (int m = tid; m < NN; m += 256) { float e = __expf(buf[m]-mx); buf[m] = e; lsum += e; }
    red[tid] = lsum; __syncthreads();
    for (int s = 128; s > 0; s >>= 1) { if (tid < s) red[tid] += red[tid+s]; __syncthreads(); }
    float inv = 1.f / red[0];
    size_t rowoff = (size_t)i * NN;
    for (int m = tid; m < NN; m += 256) {
        float s = buf[m] * inv;
#pragma unroll
        for (int k = 0; k < 3; k++) {
            float a = cheb[(size_t)k*NN*NN + rowoff + m] * s;
            unsigned h2 = bf2(0.f, a);
            float hf = __uint_as_float(h2 << 16);
            unsigned l2 = bf2(0.f, a - hf);
            size_t o = ((size_t)(k*B + b)*NN + i)*NN + m;
            g_ah[o] = (unsigned short)(h2 & 0xFFFF);
            g_al[o] = (unsigned short)(l2 & 0xFFFF);
        }
    }
}

// ---------------- K6: cp.async-fed bf16-split MMA + theta epilogue ----------------
// A pre-split in g_ah/g_al, B pre-split in g_xbh/g_xbl. 2-stage cp.async pipeline.
// smem: A stages 2x98304, B stages 2x16384 -> 229376 B. Epilogue overlays base.
#define K6_STA(s)  ((s)*98304)
#define K6_STB(s)  (196608 + (s)*16384)
#define K6_SMEM    229376
#define CS_STR     68
#define CS_K       (128*CS_STR)
#define THS_OFF    (3*CS_K)

__device__ __forceinline__ void k6_issue(int tid, uint32_t sb, int s, int b, int i0,
                                         int t0, int j0)
{
#pragma unroll
    for (int r = 0; r < 14; r++) {
        int idx = tid + 512*r;
        if (idx < 6144) {
            int k = idx >> 11, rem = idx & 2047;
            int half = rem >> 10, rr = (rem & 1023) >> 3, c = rem & 7;
            const unsigned short* base = half ? g_al : g_ah;
            const unsigned short* src = base + (((size_t)(k*B + b)*NN + (i0+rr))*NN + j0 + c*8);
            cp16(sb + K6_STA(s) + k*32768 + half*16384 + SWZ((uint32_t)(rr*128 + c*16)), src);
        } else {
            int bi = idx - 6144;
            int half = bi >> 9, rr = (bi & 511) >> 3, c = bi & 7;
            const unsigned short* base = half ? g_xbl : g_xbh;
            const unsigned short* src = base + ((size_t)b*(T*FI) + t0*32 + rr)*NN + j0 + c*8;
            cp16(sb + K6_STB(s) + half*8192 + SWZ((uint32_t)(rr*128 + c*16)), src);
        }
    }
}

__global__ __launch_bounds__(512, 1)
void k6_mma(const float* __restrict__ theta)
{
    extern __shared__ __align__(1024) char smem[];
    const int b  = blockIdx.z;
    const int i0 = blockIdx.y * 128;
    const int t0 = blockIdx.x * 2;
    const int tid = threadIdx.x, wid = tid >> 5, lane = tid & 31;
    const int g = lane >> 2, q = lane & 3;
    const int wm = wid & 3, wn = wid >> 2;
    const uint32_t sb = s2u(smem);

    const uint32_t aRow0 = (uint32_t)((wm*32 + ((lane >> 3) & 1)*8 + (lane & 7)) * 128
                                      + (lane >> 4) * 16);
    const uint32_t aRow1 = aRow0 + 16*128;
    const uint32_t bRow  = (uint32_t)((wn*16 + ((lane >> 4) & 1)*8 + (lane & 7)) * 128
                                      + ((lane >> 3) & 1) * 16);

    float acc[3][2][2][4];
#pragma unroll
    for (int k = 0; k < 3; k++)
#pragma unroll
        for (int mt = 0; mt < 2; mt++)
#pragma unroll
            for (int nt = 0; nt < 2; nt++)
#pragma unroll
                for (int c = 0; c < 4; c++) acc[k][mt][nt][c] = 0.f;

    k6_issue(tid, sb, 0, b, i0, t0, 0);
    CP_COMMIT();

    for (int it = 0; it < 32; it++) {
        const int cur = it & 1;
        if (it + 1 < 32) {
            k6_issue(tid, sb, cur ^ 1, b, i0, t0, (it + 1) * 64);
            CP_COMMIT();
            asm volatile("cp.async.wait_group 1;" ::: "memory");
        } else {
            asm volatile("cp.async.wait_group 0;" ::: "memory");
        }
        __syncthreads();

        const uint32_t A0 = sb + K6_STA(cur);
        const uint32_t Bb = sb + K6_STB(cur);
#pragma unroll
        for (int kk = 0; kk < 4; kk++) {
            const uint32_t kb = (uint32_t)kk * 32;
            unsigned bh[4], bl[4];
            ldsm4(bh[0], bh[1], bh[2], bh[3], Bb + SWZ(bRow + kb));
            ldsm4(bl[0], bl[1], bl[2], bl[3], Bb + 8192 + SWZ(bRow + kb));
#pragma unroll
            for (int k = 0; k < 3; k++) {
                const uint32_t Ak = A0 + (uint32_t)k * 32768;
                unsigned a0[4], a1[4];
                ldsm4(a0[0], a0[1], a0[2], a0[3], Ak + SWZ(aRow0 + kb));
                ldsm4(a1[0], a1[1], a1[2], a1[3], Ak + SWZ(aRow1 + kb));
                mma_bf16(acc[k][0][0], a0, bh + 0); mma_bf16(acc[k][0][1], a0, bh + 2);
                mma_bf16(acc[k][1][0], a1, bh + 0); mma_bf16(acc[k][1][1], a1, bh + 2);
                mma_bf16(acc[k][0][0], a0, bl + 0); mma_bf16(acc[k][0][1], a0, bl + 2);
                mma_bf16(acc[k][1][0], a1, bl + 0); mma_bf16(acc[k][1][1], a1, bl + 2);
                ldsm4(a0[0], a0[1], a0[2], a0[3], Ak + 16384 + SWZ(aRow0 + kb));
                ldsm4(a1[0], a1[1], a1[2], a1[3], Ak + 16384 + SWZ(aRow1 + kb));
                mma_bf16(acc[k][0][0], a0, bh + 0); mma_bf16(acc[k][0][1], a0, bh + 2);
                mma_bf16(acc[k][1][0], a1, bh + 0); mma_bf16(acc[k][1][1], a1, bh + 2);
            }
        }
        __syncthreads();
    }

    // ---- stage accumulators to smem (overlay stage area) ----
    float* Cs = (float*)smem;
#pragma unroll
    for (int k = 0; k < 3; k++)
#pragma unroll
        for (int mt = 0; mt < 2; mt++)
#pragma unroll
            for (int nt = 0; nt < 2; nt++) {
                int row = wm*32 + mt*16 + g;
                int col = wn*16 + nt*8 + q*2;
                *(float2*)(Cs + k*CS_K + row*CS_STR + col)
                    = make_float2(acc[k][mt][nt][0], acc[k][mt][nt][1]);
                *(float2*)(Cs + k*CS_K + (row + 8)*CS_STR + col)
                    = make_float2(acc[k][mt][nt][2], acc[k][mt][nt][3]);
            }
    float* ths = Cs + THS_OFF;                 // [3][32][64]
    for (int idx = tid; idx < KC*FI*FO; idx += 512) ths[idx] = theta[idx];
    __syncthreads();

    // ---- epilogue ----
    {
        const int i = tid >> 2, seg = tid & 3, o0 = seg*16;
        float out0[16], out1[16];
#pragma unroll
        for (int o = 0; o < 16; o++) { out0[o] = 0.f; out1[o] = 0.f; }
#pragma unroll
        for (int k = 0; k < 3; k++) {
            const float* cr = Cs + k*CS_K + i*CS_STR;
#pragma unroll
            for (int f4 = 0; f4 < 8; f4++) {
                float4 c0 = *(const float4*)(cr + f4*4);
                float4 c1 = *(const float4*)(cr + 32 + f4*4);
                const float* cf0 = (const float*)&c0;
                const float* cf1 = (const float*)&c1;
#pragma unroll
                for (int j = 0; j < 4; j++) {
                    float v0 = cf0[j], v1 = cf1[j];
                    const float* th = ths + (k*32 + f4*4 + j)*64 + o0;
#pragma unroll
                    for (int oq = 0; oq < 4; oq++) {
                        float4 t4 = *(const float4*)(th + oq*4);
                        out0[oq*4+0] += v0*t4.x; out0[oq*4+1] += v0*t4.y;
                        out0[oq*4+2] += v0*t4.z; out0[oq*4+3] += v0*t4.w;
                        out1[oq*4+0] += v1*t4.x; out1[oq*4+1] += v1*t4.y;
                        out1[oq*4+2] += v1*t4.z; out1[oq*4+3] += v1*t4.w;
                    }
                }
            }
        }
        size_t base0 = (((size_t)b*T + t0    )*NN + i0 + i)*FO + o0;
        size_t base1 = (((size_t)b*T + t0 + 1)*NN + i0 + i)*FO + o0;
#pragma unroll
        for (int oq = 0; oq < 4; oq++) {
            float4 v0, v1;
            v0.x = fmaxf(out0[oq*4+0], 0.f); v0.y = fmaxf(out0[oq*4+1], 0.f);
            v0.z = fmaxf(out0[oq*4+2], 0.f); v0.w = fmaxf(out0[oq*4+3], 0.f);
            v1.x = fmaxf(out1[oq*4+0], 0.f); v1.y = fmaxf(out1[oq*4+1], 0.f);
            v1.z = fmaxf(out1[oq*4+2], 0.f); v1.w = fmaxf(out1[oq*4+3], 0.f);
            *(float4*)(g_xgc + base0 + oq*4) = v0;
            *(float4*)(g_xgc + base1 + oq*4) = v1;
        }
    }
}

// ---------------- K7 ----------------
#define S7_WS   0
#define S7_XG   15232
#define S7_XR   (S7_XG + 6144)
#define S7_YB   (S7_XR + 1024)
#define S7_MU   (S7_YB + 2080)
#define S7_RI   (S7_MU + 32)
#define S7_TOTF (S7_RI + 32)

__global__ __launch_bounds__(256) void k7_final(
    const float* __restrict__ x,
    const float* __restrict__ tw, const float* __restrict__ tb,
    const float* __restrict__ rw, const float* __restrict__ rb,
    const float* __restrict__ lg, const float* __restrict__ lb,
    float* __restrict__ out)
{
    extern __shared__ float s7[];
    float* Ws = s7 + S7_WS;
    float* xg = s7 + S7_XG;
    float* xr = s7 + S7_XR;
    float* yb = s7 + S7_YB;
    float* mu = s7 + S7_MU;
    float* ri = s7 + S7_RI;

    int b = blockIdx.z, t = blockIdx.y, n0 = blockIdx.x << 5;
    int tid = threadIdx.x;

    for (int idx = tid; idx < FO*192; idx += 256) { int o = idx / 192, r = idx - o*192; Ws[r*68 + o] = tw[idx]; }
    for (int idx = tid; idx < FO*FI; idx += 256) { int o = idx >> 5, f = idx & 31; Ws[(192+f)*68 + o] = rw[idx]; }
#pragma unroll
    for (int dt = 0; dt < 3; dt++) {
        int ts = t + dt - 1;
        if (ts >= 0 && ts < T) {
            const float* src = g_xgc + (((size_t)b*T + ts)*NN + n0) * FO;
            for (int idx = tid; idx < 32*FO; idx += 256) xg[dt*2048 + idx] = src[idx];
        } else {
            for (int idx = tid; idx < 32*FO; idx += 256) xg[dt*2048 + idx] = 0.f;
        }
    }
    {
        const float* src = x + (((size_t)b*T + t)*NN + n0) * FI;
        for (int idx = tid; idx < 32*FI; idx += 256) xr[idx] = src[idx];
    }
    __syncthreads();

    int og = tid & 15, nlg = tid >> 4;
    int o0 = og << 2, nl0 = nlg << 1;
    float4 tb4 = *(const float4*)(tb + o0);
    float4 rb4 = *(const float4*)(rb + o0);
    float acc0[4], acc1[4];
#pragma unroll
    for (int c = 0; c < 4; c++) {
        float bia = ((const float*)&tb4)[c] + ((const float*)&rb4)[c];
        acc0[c] = bia; acc1[c] = bia;
    }

    for (int c = 0; c < FO; c++) {
#pragma unroll
        for (int dt = 0; dt < 3; dt++) {
            float4 w = *(const float4*)(Ws + (c*3 + dt)*68 + o0);
            float xa = xg[dt*2048 + nl0*FO + c];
            float xb2 = xg[dt*2048 + nl0*FO + FO + c];
            acc0[0] += xa*w.x;  acc0[1] += xa*w.y;  acc0[2] += xa*w.z;  acc0[3] += xa*w.w;
            acc1[0] += xb2*w.x; acc1[1] += xb2*w.y; acc1[2] += xb2*w.z; acc1[3] += xb2*w.w;
        }
    }
#pragma unroll
    for (int f = 0; f < FI; f++) {
        float4 w = *(const float4*)(Ws + (192 + f)*68 + o0);
        float xa = xr[nl0*FI + f];
        float xb2 = xr[nl0*FI + FI + f];
        acc0[0] += xa*w.x;  acc0[1] += xa*w.y;  acc0[2] += xa*w.z;  acc0[3] += xa*w.w;
        acc1[0] += xb2*w.x; acc1[1] += xb2*w.y; acc1[2] += xb2*w.z; acc1[3] += xb2*w.w;
    }
#pragma unroll
    for (int c = 0; c < 4; c++) {
        yb[nl0*65 + o0 + c]     = acc0[c] > 0.f ? acc0[c] : 0.f;
        yb[(nl0+1)*65 + o0 + c] = acc1[c] > 0.f ? acc1[c] : 0.f;
    }
    __syncthreads();
    if (tid < 32) {
        float m = 0.f;
#pragma unroll
        for (int o = 0; o < FO; o++) m += yb[tid*65 + o];
        m *= (1.f/FO);
        float v = 0.f;
#pragma unroll
        for (int o = 0; o < FO; o++) { float d = yb[tid*65 + o] - m; v += d*d; }
        v *= (1.f/FO);
        mu[tid] = m;
        ri[tid] = rsqrtf(v + 1e-5f);
    }
    __syncthreads();
    float4 g4 = *(const float4*)(lg + o0);
    float4 b4 = *(const float4*)(lb + o0);
#pragma unroll
    for (int j = 0; j < 2; j++) {
        int nl = nl0 + j;
        float m = mu[nl], r = ri[nl];
        float4 ov;
        ov.x = (yb[nl*65 + o0 + 0] - m)*r*g4.x + b4.x;
        ov.y = (yb[nl*65 + o0 + 1] - m)*r*g4.y + b4.y;
        ov.z = (yb[nl*65 + o0 + 2] - m)*r*g4.z + b4.z;
        ov.w = (yb[nl*65 + o0 + 3] - m)*r*g4.w + b4.w;
        *(float4*)(out + ((((size_t)b*T + t)*NN + n0 + nl) << 6) + o0) = ov;
    }
}

// ---------------- launch ----------------
extern "C" void kernel_launch(void* const* d_in, const int* in_sizes, int n_in,
                              void* d_out, int out_size)
{
    const float* x     = (const float*)d_in[0];
    const float* cheb  = (const float*)d_in[1];
    const float* wq_t  = (const float*)d_in[2];
    const float* wk_t  = (const float*)d_in[3];
    const float* wq_s  = (const float*)d_in[4];
    const float* wk_s  = (const float*)d_in[5];
    const float* theta = (const float*)d_in[6];
    const float* tw    = (const float*)d_in[7];
    const float* tbv   = (const float*)d_in[8];
    const float* rw    = (const float*)d_in[9];
    const float* rbv   = (const float*)d_in[10];
    const float* lg    = (const float*)d_in[11];
    const float* lb    = (const float*)d_in[12];
    float* out = (float*)d_out;

    cudaFuncSetAttribute(k6_mma, cudaFuncAttributeMaxDynamicSharedMemorySize, K6_SMEM);
    cudaFuncSetAttribute(k7_final, cudaFuncAttributeMaxDynamicSharedMemorySize,
                         S7_TOTF * (int)sizeof(float));

    k1_qk<<<(B*T*NN)/256, 256>>>(x, wq_t, wk_t);
    k2_ta<<<B*T, 256>>>();
    k3_xta<<<dim3(NN/32, B), 1024>>>(x);
    k3b_cvt<<<dim3(NN/32, T, B), 256>>>();
    k4_qk<<<(B*T*NN)/256, 256>>>(wq_s, wk_s);
    k5_sa<<<B*NN, 256>>>(cheb);
    k6_mma<<<dim3(T/2, NN/128, B), 512, K6_SMEM>>>(theta);
    k7_final<<<dim3(NN/32, T, B), 256, S7_TOTF * (int)sizeof(float)>>>(
        x, tw, tbv, rw, rbv, lg, lb, out);
}

// round 15
// speedup vs baseline: 2.3800x; 1.6388x over previous
#include <cuda_runtime.h>
#include <math.h>
#include <stdint.h>

#define B   16
#define T   12
#define NN  2048
#define FI  32
#define FO  64
#define KC  3

// ---------------- static scratch (no allocations allowed) ----------------
__device__ float g_qt[(size_t)B*T*NN];
__device__ float g_kt[(size_t)B*T*NN];
__device__ float g_ta[(size_t)B*T*T];
__device__ __align__(16) float g_xta[(size_t)B*T*NN*FI];
__device__ __align__(16) float g_qs[(size_t)B*NN*T];
__device__ __align__(16) float g_ks[(size_t)B*NN*T];
__device__ __align__(16) float g_xgc[(size_t)B*T*NN*FO];
// pre-split A = cheb_k * sa : bf16 hi/lo, [k][b][i][j]
__device__ __align__(16) unsigned short g_ah[(size_t)KC*B*NN*NN];
__device__ __align__(16) unsigned short g_al[(size_t)KC*B*NN*NN];
// pre-split x_ta transposed: [b][t*32+f][n]
__device__ __align__(16) unsigned short g_xbh[(size_t)B*T*FI*NN];
__device__ __align__(16) unsigned short g_xbl[(size_t)B*T*FI*NN];

__device__ __forceinline__ unsigned bf2(float h, float l) {
    unsigned r;
    asm("cvt.rn.bf16x2.f32 %0, %1, %2;" : "=r"(r) : "f"(h), "f"(l));
    return r;
}
__device__ __forceinline__ void mma_bf16(float* c, const unsigned* a, const unsigned* b) {
    asm volatile(
        "mma.sync.aligned.m16n8k16.row.col.f32.bf16.bf16.f32 "
        "{%0,%1,%2,%3}, {%4,%5,%6,%7}, {%8,%9}, {%0,%1,%2,%3};"
        : "+f"(c[0]), "+f"(c[1]), "+f"(c[2]), "+f"(c[3])
        : "r"(a[0]), "r"(a[1]), "r"(a[2]), "r"(a[3]), "r"(b[0]), "r"(b[1]));
}
__device__ __forceinline__ void ldsm4(unsigned& r0, unsigned& r1, unsigned& r2, unsigned& r3,
                                      uint32_t a) {
    asm volatile("ldmatrix.sync.aligned.m8n8.x4.shared.b16 {%0,%1,%2,%3}, [%4];"
                 : "=r"(r0), "=r"(r1), "=r"(r2), "=r"(r3) : "r"(a));
}
__device__ __forceinline__ void ldsm2(unsigned& r0, unsigned& r1, uint32_t a) {
    asm volatile("ldmatrix.sync.aligned.m8n8.x2.shared.b16 {%0,%1}, [%2];"
                 : "=r"(r0), "=r"(r1) : "r"(a));
}
__device__ __forceinline__ uint32_t s2u(const void* p) {
    uint32_t a;
    asm("{ .reg .u64 t; cvta.to.shared.u64 t, %1; cvt.u32.u64 %0, t; }" : "=r"(a) : "l"(p));
    return a;
}
__device__ __forceinline__ void cp16(uint32_t dst, const void* src) {
    asm volatile("cp.async.cg.shared.global [%0], [%1], 16;" :: "r"(dst), "l"(src));
}
#define CP_COMMIT() asm volatile("cp.async.commit_group;" ::: "memory")
#define SWZ(o) ((o) ^ (((o) >> 3) & 0x70))

// ---------------- K1 ----------------
__global__ void k1_qk(const float* __restrict__ x,
                      const float* __restrict__ wq, const float* __restrict__ wk)
{
    __shared__ float sw[64];
    int tid = threadIdx.x;
    if (tid < 64) sw[tid] = (tid < 32) ? wq[tid] : wk[tid - 32];
    __syncthreads();
    size_t g = (size_t)blockIdx.x * 256 + tid;
    const float4* xr = (const float4*)(x + g * FI);
    float aq = 0.f, ak = 0.f;
#pragma unroll
    for (int u = 0; u < 8; u++) {
        float4 v = xr[u];
        aq += v.x*sw[u*4+0] + v.y*sw[u*4+1] + v.z*sw[u*4+2] + v.w*sw[u*4+3];
        ak += v.x*sw[32+u*4+0] + v.y*sw[32+u*4+1] + v.z*sw[32+u*4+2] + v.w*sw[32+u*4+3];
    }
    g_qt[g] = aq; g_kt[g] = ak;
}

// ---------------- K2 ----------------
__global__ void k2_ta()
{
    int b = blockIdx.x / T, t = blockIdx.x % T;
    int tid = threadIdx.x;
    const float* q  = g_qt + ((size_t)b*T + t) * NN;
    const float* kb = g_kt + (size_t)b*T*NN;
    float p[T];
#pragma unroll
    for (int s = 0; s < T; s++) p[s] = 0.f;
    for (int n = tid; n < NN; n += 256) {
        float qv = q[n];
#pragma unroll
        for (int s = 0; s < T; s++) p[s] += qv * kb[(size_t)s*NN + n];
    }
    __shared__ float sc[T];
    if (tid < T) sc[tid] = 0.f;
    __syncthreads();
#pragma unroll
    for (int s = 0; s < T; s++) {
        float v = p[s];
        for (int off = 16; off; off >>= 1) v += __shfl_down_sync(0xffffffffu, v, off);
        if ((tid & 31) == 0) atomicAdd(&sc[s], v);
    }
    __syncthreads();
    if (tid == 0) {
        const float isN = 0.022097086912079612f;
        float sv[T], mx = -1e30f;
#pragma unroll
        for (int s = 0; s < T; s++) { sv[s] = sc[s]*isN; mx = fmaxf(mx, sv[s]); }
        float sum = 0.f;
#pragma unroll
        for (int s = 0; s < T; s++) { sv[s] = __expf(sv[s]-mx); sum += sv[s]; }
        float inv = 1.f / sum;
        float* out = g_ta + ((size_t)b*T + t) * T;
#pragma unroll
        for (int s = 0; s < T; s++) out[s] = sv[s]*inv;
    }
}

// ---------------- K3 ----------------
__global__ __launch_bounds__(1024) void k3_xta(const float* __restrict__ x)
{
    __shared__ float tas[T*T];
    int b = blockIdx.y, n0 = blockIdx.x << 5;
    int tid = threadIdx.x;
    if (tid < T*T) tas[tid] = g_ta[(size_t)b*T*T + tid];
    __syncthreads();
    int f = tid & 31, nl = tid >> 5;
    size_t base = ((size_t)b*T*NN + (n0 + nl)) * FI + f;
    float v[T];
#pragma unroll
    for (int s = 0; s < T; s++) v[s] = x[base + (size_t)s*NN*FI];
#pragma unroll
    for (int t = 0; t < T; t++) {
        float a = 0.f;
#pragma unroll
        for (int s = 0; s < T; s++) a += tas[t*T + s] * v[s];
        g_xta[base + (size_t)t*NN*FI] = a;
    }
}

// ---------------- K3b: x_ta -> bf16 hi/lo, transposed [b][t*32+f][n] ----------------
__global__ __launch_bounds__(256) void k3b_cvt()
{
    __shared__ unsigned short sh[32][36];
    __shared__ unsigned short sl[32][36];
    int b = blockIdx.z, t = blockIdx.y, n0 = blockIdx.x << 5;
    int tid = threadIdx.x;
    int n_l = tid >> 3, fq = tid & 7;
    float4 v = *(const float4*)(g_xta + (((size_t)b*T + t)*NN + n0 + n_l)*FI + fq*4);
    const float* vf = (const float*)&v;
#pragma unroll
    for (int j = 0; j < 4; j++) {
        float xv = vf[j];
        unsigned h2 = bf2(0.f, xv);
        float hf = __uint_as_float(h2 << 16);
        unsigned l2 = bf2(0.f, xv - hf);
        sh[fq*4 + j][n_l] = (unsigned short)(h2 & 0xFFFF);
        sl[fq*4 + j][n_l] = (unsigned short)(l2 & 0xFFFF);
    }
    __syncthreads();
    int f = tid >> 3, nq = tid & 7;
    size_t o = ((size_t)b*(T*FI) + t*32 + f)*NN + n0 + nq*4;
    uint2 hp = make_uint2((unsigned)sh[f][nq*4+0] | ((unsigned)sh[f][nq*4+1] << 16),
                          (unsigned)sh[f][nq*4+2] | ((unsigned)sh[f][nq*4+3] << 16));
    uint2 lp = make_uint2((unsigned)sl[f][nq*4+0] | ((unsigned)sl[f][nq*4+1] << 16),
                          (unsigned)sl[f][nq*4+2] | ((unsigned)sl[f][nq*4+3] << 16));
    *(uint2*)(g_xbh + o) = hp;
    *(uint2*)(g_xbl + o) = lp;
}

// ---------------- K4 ----------------
__global__ void k4_qk(const float* __restrict__ wq, const float* __restrict__ wk)
{
    __shared__ float sw[64];
    int tid = threadIdx.x;
    if (tid < 64) sw[tid] = (tid < 32) ? wq[tid] : wk[tid - 32];
    __syncthreads();
    size_t g = (size_t)blockIdx.x * 256 + tid;
    const float4* xr = (const float4*)(g_xta + g * FI);
    float aq = 0.f, ak = 0.f;
#pragma unroll
    for (int u = 0; u < 8; u++) {
        float4 v = xr[u];
        aq += v.x*sw[u*4+0] + v.y*sw[u*4+1] + v.z*sw[u*4+2] + v.w*sw[u*4+3];
        ak += v.x*sw[32+u*4+0] + v.y*sw[32+u*4+1] + v.z*sw[32+u*4+2] + v.w*sw[32+u*4+3];
    }
    int n = (int)(g % NN);
    size_t bt = g / NN;
    int t = (int)(bt % T);
    int b = (int)(bt / T);
    size_t o = ((size_t)b*NN + n) * T + t;
    g_qs[o] = aq; g_ks[o] = ak;
}

// ---------------- K5: spatial attention, fused cheb-mul + bf16 split store ----------------
__global__ __launch_bounds__(256) void k5_sa(const float* __restrict__ cheb)
{
    __shared__ float buf[NN];
    __shared__ float red[256];
    __shared__ float qr[T];
    int b = blockIdx.x >> 11;
    int i = blockIdx.x & (NN - 1);
    int tid = threadIdx.x;
    const float* qsb = g_qs + ((size_t)b*NN + i) * T;
    const float* ksb = g_ks + (size_t)b*NN*T;
    if (tid < T) qr[tid] = qsb[tid];
    __syncthreads();
    const float isT = 0.28867513459481287f;
    float lmax = -1e30f;
    for (int m = tid; m < NN; m += 256) {
        const float4* kr = (const float4*)(ksb + (size_t)m * T);
        float4 A = kr[0], Bv = kr[1], C = kr[2];
        float s = qr[0]*A.x + qr[1]*A.y + qr[2]*A.z + qr[3]*A.w
                + qr[4]*Bv.x + qr[5]*Bv.y + qr[6]*Bv.z + qr[7]*Bv.w
                + qr[8]*C.x + qr[9]*C.y + qr[10]*C.z + qr[11]*C.w;
        s *= isT;
        buf[m] = s;
        lmax = fmaxf(lmax, s);
    }
    red[tid] = lmax; __syncthreads();
    for (int s = 128; s > 0; s >>= 1) { if (tid < s) red[tid] = fmaxf(red[tid], red[tid+s]); __syncthreads(); }
    float mx = red[0]; __syncthreads();
    float lsum = 0.f;
    for (int m = tid; m < NN; m += 256) { float e = __expf(buf[m]-mx); buf[m] = e; lsum += e; }
    red[tid] = lsum; __syncthreads();
    for (int s = 128; s > 0; s >>= 1) { if (tid < s) red[tid] += red[tid+s]; __syncthreads(); }
    float inv = 1.f / red[0];
    size_t rowoff = (size_t)i * NN;
    for (int m = tid; m < NN; m += 256) {
        float s = buf[m] * inv;
#pragma unroll
        for (int k = 0; k < 3; k++) {
            float a = cheb[(size_t)k*NN*NN + rowoff + m] * s;
            unsigned h2 = bf2(0.f, a);
            float hf = __uint_as_float(h2 << 16);
            unsigned l2 = bf2(0.f, a - hf);
            size_t o = ((size_t)(k*B + b)*NN + i)*NN + m;
            g_ah[o] = (unsigned short)(h2 & 0xFFFF);
            g_al[o] = (unsigned short)(l2 & 0xFFFF);
        }
    }
}

// ---------------- K6: 16m x 384n x 2048k bf16-split MMA; A read once chip-wide ----------
// Block (i0 = 16-row strip, b). 512 thr = 16 warps, 1m x 16n, warp tile 16 x 24.
// stage = A(3k x 16 x 128B x hi/lo = 12KB) + B(384 x 128B x hi/lo = 96KB) = 108KB; x2.
#define ST_BYTES 110592
#define K6_SMEM  221184

__device__ __forceinline__ void k6_issue(int tid, uint32_t sb, int s, int b, int i0, int j0)
{
    uint32_t base = sb + (uint32_t)s * ST_BYTES;
#pragma unroll
    for (int r = 0; r < 14; r++) {
        int idx = tid + 512*r;
        if (idx < 768) {
            int k = idx >> 8, rem = idx & 255;
            int half = rem >> 7, rr = (rem >> 3) & 15, c = rem & 7;
            const unsigned short* src = (half ? g_al : g_ah)
                + (((size_t)(k*B + b)*NN + (i0 + rr))*NN + j0 + c*8);
            cp16(base + k*4096 + half*2048 + SWZ((uint32_t)(rr*128 + c*16)), src);
        } else if (idx < 6912) {
            int bi = idx - 768;
            int rr = bi >> 4, half = (bi >> 3) & 1, c = bi & 7;
            const unsigned short* src = (half ? g_xbl : g_xbh)
                + ((size_t)b*(T*FI) + rr)*NN + j0 + c*8;
            cp16(base + 12288 + half*49152 + SWZ((uint32_t)(rr*128 + c*16)), src);
        }
    }
}

__global__ __launch_bounds__(512, 1)
void k6_mma(const float* __restrict__ theta)
{
    extern __shared__ __align__(1024) char smem[];
    const int b  = blockIdx.y;
    const int i0 = blockIdx.x << 4;
    const int tid = threadIdx.x, wid = tid >> 5, lane = tid & 31;
    const int g = lane >> 2, q = lane & 3;
    const int wn = wid;
    const uint32_t sb = s2u(smem);

    const uint32_t aRow  = (uint32_t)((((lane >> 3) & 1)*8 + (lane & 7))*128 + (lane >> 4)*16);
    const uint32_t bRow4 = (uint32_t)((wn*24 + ((lane >> 4) & 1)*8 + (lane & 7))*128
                                      + ((lane >> 3) & 1)*16);
    const uint32_t bRow2 = (uint32_t)((wn*24 + 16 + (lane & 7))*128 + ((lane >> 3) & 1)*16);

    float acc[3][3][4];
#pragma unroll
    for (int k = 0; k < 3; k++)
#pragma unroll
        for (int nt = 0; nt < 3; nt++)
#pragma unroll
            for (int c = 0; c < 4; c++) acc[k][nt][c] = 0.f;

    k6_issue(tid, sb, 0, b, i0, 0);
    CP_COMMIT();

    for (int it = 0; it < 32; it++) {
        const int cur = it & 1;
        if (it + 1 < 32) {
            k6_issue(tid, sb, cur ^ 1, b, i0, (it + 1) * 64);
            CP_COMMIT();
            asm volatile("cp.async.wait_group 1;" ::: "memory");
        } else {
            asm volatile("cp.async.wait_group 0;" ::: "memory");
        }
        __syncthreads();

        const uint32_t A0  = sb + (uint32_t)cur * ST_BYTES;
        const uint32_t Bhi = A0 + 12288;
        const uint32_t Blo = Bhi + 49152;
#pragma unroll
        for (int kk = 0; kk < 4; kk++) {
            const uint32_t kb = (uint32_t)kk * 32;
            unsigned bh[6], bl[6];
            ldsm4(bh[0], bh[1], bh[2], bh[3], Bhi + SWZ(bRow4 + kb));
            ldsm2(bh[4], bh[5],               Bhi + SWZ(bRow2 + kb));
            ldsm4(bl[0], bl[1], bl[2], bl[3], Blo + SWZ(bRow4 + kb));
            ldsm2(bl[4], bl[5],               Blo + SWZ(bRow2 + kb));
#pragma unroll
            for (int k = 0; k < 3; k++) {
                const uint32_t Ak = A0 + (uint32_t)k * 4096;
                unsigned ah[4], al[4];
                ldsm4(ah[0], ah[1], ah[2], ah[3], Ak + SWZ(aRow + kb));
                ldsm4(al[0], al[1], al[2], al[3], Ak + 2048 + SWZ(aRow + kb));
                mma_bf16(acc[k][0], ah, bh + 0);
                mma_bf16(acc[k][1], ah, bh + 2);
                mma_bf16(acc[k][2], ah, bh + 4);
                mma_bf16(acc[k][0], ah, bl + 0);
                mma_bf16(acc[k][1], ah, bl + 2);
                mma_bf16(acc[k][2], ah, bl + 4);
                mma_bf16(acc[k][0], al, bh + 0);
                mma_bf16(acc[k][1], al, bh + 2);
                mma_bf16(acc[k][2], al, bh + 4);
            }
        }
        __syncthreads();
    }

    // ---- epilogue: theta contraction + relu, write g_xgc ----
    float* Cs  = (float*)smem;                  // [16][392]
    float* ths = (float*)(smem + 25600);        // [3][32][64]
    for (int idx = tid; idx < KC*FI*FO; idx += 512) ths[idx] = theta[idx];

    const int i = wid, og2 = (lane | ((tid & 256) ? 32 : 0));  // careful: need 32 o-pairs
    // remap: thread handles (row i = tid>>5, o-pair og2 = (tid&31)*2)
    const int row = tid >> 5;
    const int op  = (tid & 31) * 2;
    (void)i; (void)og2;

    float out[T][2];
#pragma unroll
    for (int t = 0; t < T; t++) { out[t][0] = 0.f; out[t][1] = 0.f; }

#pragma unroll
    for (int k = 0; k < 3; k++) {
        __syncthreads();
#pragma unroll
        for (int nt = 0; nt < 3; nt++) {
            int col = wn*24 + nt*8 + q*2;
            Cs[g*392 + col]     = acc[k][nt][0];
            Cs[g*392 + col + 1] = acc[k][nt][1];
            Cs[(g+8)*392 + col]     = acc[k][nt][2];
            Cs[(g+8)*392 + col + 1] = acc[k][nt][3];
        }
        __syncthreads();
        const float* cr = Cs + row*392;
#pragma unroll
        for (int f = 0; f < FI; f++) {
            float2 tv = *(const float2*)(ths + (k*FI + f)*FO + op);
#pragma unroll
            for (int t = 0; t < T; t++) {
                float cv = cr[t*32 + f];
                out[t][0] += cv * tv.x;
                out[t][1] += cv * tv.y;
            }
        }
    }
#pragma unroll
    for (int t = 0; t < T; t++) {
        float2 v;
        v.x = fmaxf(out[t][0], 0.f);
        v.y = fmaxf(out[t][1], 0.f);
        *(float2*)(g_xgc + (((size_t)b*T + t)*NN + i0 + row)*FO + op) = v;
    }
}

// ---------------- K7 ----------------
#define S7_WS   0
#define S7_XG   15232
#define S7_XR   (S7_XG + 6144)
#define S7_YB   (S7_XR + 1024)
#define S7_MU   (S7_YB + 2080)
#define S7_RI   (S7_MU + 32)
#define S7_TOTF (S7_RI + 32)

__global__ __launch_bounds__(256) void k7_final(
    const float* __restrict__ x,
    const float* __restrict__ tw, const float* __restrict__ tb,
    const float* __restrict__ rw, const float* __restrict__ rb,
    const float* __restrict__ lg, const float* __restrict__ lb,
    float* __restrict__ out)
{
    extern __shared__ float s7[];
    float* Ws = s7 + S7_WS;
    float* xg = s7 + S7_XG;
    float* xr = s7 + S7_XR;
    float* yb = s7 + S7_YB;
    float* mu = s7 + S7_MU;
    float* ri = s7 + S7_RI;

    int b = blockIdx.z, t = blockIdx.y, n0 = blockIdx.x << 5;
    int tid = threadIdx.x;

    for (int idx = tid; idx < FO*192; idx += 256) { int o = idx / 192, r = idx - o*192; Ws[r*68 + o] = tw[idx]; }
    for (int idx = tid; idx < FO*FI; idx += 256) { int o = idx >> 5, f = idx & 31; Ws[(192+f)*68 + o] = rw[idx]; }
#pragma unroll
    for (int dt = 0; dt < 3; dt++) {
        int ts = t + dt - 1;
        if (ts >= 0 && ts < T) {
            const float* src = g_xgc + (((size_t)b*T + ts)*NN + n0) * FO;
            for (int idx = tid; idx < 32*FO; idx += 256) xg[dt*2048 + idx] = src[idx];
        } else {
            for (int idx = tid; idx < 32*FO; idx += 256) xg[dt*2048 + idx] = 0.f;
        }
    }
    {
        const float* src = x + (((size_t)b*T + t)*NN + n0) * FI;
        for (int idx = tid; idx < 32*FI; idx += 256) xr[idx] = src[idx];
    }
    __syncthreads();

    int og = tid & 15, nlg = tid >> 4;
    int o0 = og << 2, nl0 = nlg << 1;
    float4 tb4 = *(const float4*)(tb + o0);
    float4 rb4 = *(const float4*)(rb + o0);
    float acc0[4], acc1[4];
#pragma unroll
    for (int c = 0; c < 4; c++) {
        float bia = ((const float*)&tb4)[c] + ((const float*)&rb4)[c];
        acc0[c] = bia; acc1[c] = bia;
    }

    for (int c = 0; c < FO; c++) {
#pragma unroll
        for (int dt = 0; dt < 3; dt++) {
            float4 w = *(const float4*)(Ws + (c*3 + dt)*68 + o0);
            float xa = xg[dt*2048 + nl0*FO + c];
            float xb2 = xg[dt*2048 + nl0*FO + FO + c];
            acc0[0] += xa*w.x;  acc0[1] += xa*w.y;  acc0[2] += xa*w.z;  acc0[3] += xa*w.w;
            acc1[0] += xb2*w.x; acc1[1] += xb2*w.y; acc1[2] += xb2*w.z; acc1[3] += xb2*w.w;
        }
    }
#pragma unroll
    for (int f = 0; f < FI; f++) {
        float4 w = *(const float4*)(Ws + (192 + f)*68 + o0);
        float xa = xr[nl0*FI + f];
        float xb2 = xr[nl0*FI + FI + f];
        acc0[0] += xa*w.x;  acc0[1] += xa*w.y;  acc0[2] += xa*w.z;  acc0[3] += xa*w.w;
        acc1[0] += xb2*w.x; acc1[1] += xb2*w.y; acc1[2] += xb2*w.z; acc1[3] += xb2*w.w;
    }
#pragma unroll
    for (int c = 0; c < 4; c++) {
        yb[nl0*65 + o0 + c]     = acc0[c] > 0.f ? acc0[c] : 0.f;
        yb[(nl0+1)*65 + o0 + c] = acc1[c] > 0.f ? acc1[c] : 0.f;
    }
    __syncthreads();
    if (tid < 32) {
        float m = 0.f;
#pragma unroll
        for (int o = 0; o < FO; o++) m += yb[tid*65 + o];
        m *= (1.f/FO);
        float v = 0.f;
#pragma unroll
        for (int o = 0; o < FO; o++) { float d = yb[tid*65 + o] - m; v += d*d; }
        v *= (1.f/FO);
        mu[tid] = m;
        ri[tid] = rsqrtf(v + 1e-5f);
    }
    __syncthreads();
    float4 g4 = *(const float4*)(lg + o0);
    float4 b4 = *(const float4*)(lb + o0);
#pragma unroll
    for (int j = 0; j < 2; j++) {
        int nl = nl0 + j;
        float m = mu[nl], r = ri[nl];
        float4 ov;
        ov.x = (yb[nl*65 + o0 + 0] - m)*r*g4.x + b4.x;
        ov.y = (yb[nl*65 + o0 + 1] - m)*r*g4.y + b4.y;
        ov.z = (yb[nl*65 + o0 + 2] - m)*r*g4.z + b4.z;
        ov.w = (yb[nl*65 + o0 + 3] - m)*r*g4.w + b4.w;
        *(float4*)(out + ((((size_t)b*T + t)*NN + n0 + nl) << 6) + o0) = ov;
    }
}

// ---------------- launch ----------------
extern "C" void kernel_launch(void* const* d_in, const int* in_sizes, int n_in,
                              void* d_out, int out_size)
{
    const float* x     = (const float*)d_in[0];
    const float* cheb  = (const float*)d_in[1];
    const float* wq_t  = (const float*)d_in[2];
    const float* wk_t  = (const float*)d_in[3];
    const float* wq_s  = (const float*)d_in[4];
    const float* wk_s  = (const float*)d_in[5];
    const float* theta = (const float*)d_in[6];
    const float* tw    = (const float*)d_in[7];
    const float* tbv   = (const float*)d_in[8];
    const float* rw    = (const float*)d_in[9];
    const float* rbv   = (const float*)d_in[10];
    const float* lg    = (const float*)d_in[11];
    const float* lb    = (const float*)d_in[12];
    float* out = (float*)d_out;

    cudaFuncSetAttribute(k6_mma, cudaFuncAttributeMaxDynamicSharedMemorySize, K6_SMEM);
    cudaFuncSetAttribute(k7_final, cudaFuncAttributeMaxDynamicSharedMemorySize,
                         S7_TOTF * (int)sizeof(float));

    k1_qk<<<(B*T*NN)/256, 256>>>(x, wq_t, wk_t);
    k2_ta<<<B*T, 256>>>();
    k3_xta<<<dim3(NN/32, B), 1024>>>(x);
    k3b_cvt<<<dim3(NN/32, T, B), 256>>>();
    k4_qk<<<(B*T*NN)/256, 256>>>(wq_s, wk_s);
    k5_sa<<<B*NN, 256>>>(cheb);
    k6_mma<<<dim3(NN/16, B), 512, K6_SMEM>>>(theta);
    k7_final<<<dim3(NN/32, T, B), 256, S7_TOTF * (int)sizeof(float)>>>(
        x, tw, tbv, rw, rbv, lg, lb, out);
}

// round 16
// speedup vs baseline: 2.3944x; 1.0061x over previous
#include <cuda_runtime.h>
#include <math.h>
#include <stdint.h>

#define B   16
#define T   12
#define NN  2048
#define FI  32
#define FO  64
#define KC  3

// ---------------- static scratch (no allocations allowed) ----------------
__device__ float g_qt[(size_t)B*T*NN];
__device__ float g_kt[(size_t)B*T*NN];
__device__ float g_ta[(size_t)B*T*T];
__device__ __align__(16) float g_xta[(size_t)B*T*NN*FI];
__device__ __align__(16) float g_qs[(size_t)B*NN*T];
__device__ __align__(16) float g_ks[(size_t)B*NN*T];
__device__ __align__(16) float g_xgc[(size_t)B*T*NN*FO];
// pre-split A = cheb_k * sa : bf16 hi/lo, [k][b][i][j]
__device__ __align__(16) unsigned short g_ah[(size_t)KC*B*NN*NN];
__device__ __align__(16) unsigned short g_al[(size_t)KC*B*NN*NN];
// pre-split x_ta transposed: [b][t*32+f][n]
__device__ __align__(16) unsigned short g_xbh[(size_t)B*T*FI*NN];
__device__ __align__(16) unsigned short g_xbl[(size_t)B*T*FI*NN];

__device__ __forceinline__ unsigned bf2(float h, float l) {
    unsigned r;
    asm("cvt.rn.bf16x2.f32 %0, %1, %2;" : "=r"(r) : "f"(h), "f"(l));
    return r;
}
__device__ __forceinline__ void mma_bf16(float* c, const unsigned* a, const unsigned* b) {
    asm volatile(
        "mma.sync.aligned.m16n8k16.row.col.f32.bf16.bf16.f32 "
        "{%0,%1,%2,%3}, {%4,%5,%6,%7}, {%8,%9}, {%0,%1,%2,%3};"
        : "+f"(c[0]), "+f"(c[1]), "+f"(c[2]), "+f"(c[3])
        : "r"(a[0]), "r"(a[1]), "r"(a[2]), "r"(a[3]), "r"(b[0]), "r"(b[1]));
}
__device__ __forceinline__ void ldsm4(unsigned& r0, unsigned& r1, unsigned& r2, unsigned& r3,
                                      uint32_t a) {
    asm volatile("ldmatrix.sync.aligned.m8n8.x4.shared.b16 {%0,%1,%2,%3}, [%4];"
                 : "=r"(r0), "=r"(r1), "=r"(r2), "=r"(r3) : "r"(a));
}
__device__ __forceinline__ void ldsm2(unsigned& r0, unsigned& r1, uint32_t a) {
    asm volatile("ldmatrix.sync.aligned.m8n8.x2.shared.b16 {%0,%1}, [%2];"
                 : "=r"(r0), "=r"(r1) : "r"(a));
}
__device__ __forceinline__ uint32_t s2u(const void* p) {
    uint32_t a;
    asm("{ .reg .u64 t; cvta.to.shared.u64 t, %1; cvt.u32.u64 %0, t; }" : "=r"(a) : "l"(p));
    return a;
}
__device__ __forceinline__ void cp16(uint32_t dst, const void* src) {
    asm volatile("cp.async.cg.shared.global [%0], [%1], 16;" :: "r"(dst), "l"(src));
}
#define CP_COMMIT() asm volatile("cp.async.commit_group;" ::: "memory")
#define SWZ(o) ((o) ^ (((o) >> 3) & 0x70))

// ---------------- K1 ----------------
__global__ void k1_qk(const float* __restrict__ x,
                      const float* __restrict__ wq, const float* __restrict__ wk)
{
    __shared__ float sw[64];
    int tid = threadIdx.x;
    if (tid < 64) sw[tid] = (tid < 32) ? wq[tid] : wk[tid - 32];
    __syncthreads();
    size_t g = (size_t)blockIdx.x * 256 + tid;
    const float4* xr = (const float4*)(x + g * FI);
    float aq = 0.f, ak = 0.f;
#pragma unroll
    for (int u = 0; u < 8; u++) {
        float4 v = xr[u];
        aq += v.x*sw[u*4+0] + v.y*sw[u*4+1] + v.z*sw[u*4+2] + v.w*sw[u*4+3];
        ak += v.x*sw[32+u*4+0] + v.y*sw[32+u*4+1] + v.z*sw[32+u*4+2] + v.w*sw[32+u*4+3];
    }
    g_qt[g] = aq; g_kt[g] = ak;
}

// ---------------- K2 ----------------
__global__ void k2_ta()
{
    int b = blockIdx.x / T, t = blockIdx.x % T;
    int tid = threadIdx.x;
    const float* q  = g_qt + ((size_t)b*T + t) * NN;
    const float* kb = g_kt + (size_t)b*T*NN;
    float p[T];
#pragma unroll
    for (int s = 0; s < T; s++) p[s] = 0.f;
    for (int n = tid; n < NN; n += 256) {
        float qv = q[n];
#pragma unroll
        for (int s = 0; s < T; s++) p[s] += qv * kb[(size_t)s*NN + n];
    }
    __shared__ float sc[T];
    if (tid < T) sc[tid] = 0.f;
    __syncthreads();
#pragma unroll
    for (int s = 0; s < T; s++) {
        float v = p[s];
        for (int off = 16; off; off >>= 1) v += __shfl_down_sync(0xffffffffu, v, off);
        if ((tid & 31) == 0) atomicAdd(&sc[s], v);
    }
    __syncthreads();
    if (tid == 0) {
        const float isN = 0.022097086912079612f;
        float sv[T], mx = -1e30f;
#pragma unroll
        for (int s = 0; s < T; s++) { sv[s] = sc[s]*isN; mx = fmaxf(mx, sv[s]); }
        float sum = 0.f;
#pragma unroll
        for (int s = 0; s < T; s++) { sv[s] = __expf(sv[s]-mx); sum += sv[s]; }
        float inv = 1.f / sum;
        float* out = g_ta + ((size_t)b*T + t) * T;
#pragma unroll
        for (int s = 0; s < T; s++) out[s] = sv[s]*inv;
    }
}

// ---------------- K3 ----------------
__global__ __launch_bounds__(1024) void k3_xta(const float* __restrict__ x)
{
    __shared__ float tas[T*T];
    int b = blockIdx.y, n0 = blockIdx.x << 5;
    int tid = threadIdx.x;
    if (tid < T*T) tas[tid] = g_ta[(size_t)b*T*T + tid];
    __syncthreads();
    int f = tid & 31, nl = tid >> 5;
    size_t base = ((size_t)b*T*NN + (n0 + nl)) * FI + f;
    float v[T];
#pragma unroll
    for (int s = 0; s < T; s++) v[s] = x[base + (size_t)s*NN*FI];
#pragma unroll
    for (int t = 0; t < T; t++) {
        float a = 0.f;
#pragma unroll
        for (int s = 0; s < T; s++) a += tas[t*T + s] * v[s];
        g_xta[base + (size_t)t*NN*FI] = a;
    }
}

// ---------------- K3b: x_ta -> bf16 hi/lo, transposed [b][t*32+f][n] ----------------
__global__ __launch_bounds__(256) void k3b_cvt()
{
    __shared__ unsigned short sh[32][36];
    __shared__ unsigned short sl[32][36];
    int b = blockIdx.z, t = blockIdx.y, n0 = blockIdx.x << 5;
    int tid = threadIdx.x;
    int n_l = tid >> 3, fq = tid & 7;
    float4 v = *(const float4*)(g_xta + (((size_t)b*T + t)*NN + n0 + n_l)*FI + fq*4);
    const float* vf = (const float*)&v;
#pragma unroll
    for (int j = 0; j < 4; j++) {
        float xv = vf[j];
        unsigned h2 = bf2(0.f, xv);
        float hf = __uint_as_float(h2 << 16);
        unsigned l2 = bf2(0.f, xv - hf);
        sh[fq*4 + j][n_l] = (unsigned short)(h2 & 0xFFFF);
        sl[fq*4 + j][n_l] = (unsigned short)(l2 & 0xFFFF);
    }
    __syncthreads();
    int f = tid >> 3, nq = tid & 7;
    size_t o = ((size_t)b*(T*FI) + t*32 + f)*NN + n0 + nq*4;
    uint2 hp = make_uint2((unsigned)sh[f][nq*4+0] | ((unsigned)sh[f][nq*4+1] << 16),
                          (unsigned)sh[f][nq*4+2] | ((unsigned)sh[f][nq*4+3] << 16));
    uint2 lp = make_uint2((unsigned)sl[f][nq*4+0] | ((unsigned)sl[f][nq*4+1] << 16),
                          (unsigned)sl[f][nq*4+2] | ((unsigned)sl[f][nq*4+3] << 16));
    *(uint2*)(g_xbh + o) = hp;
    *(uint2*)(g_xbl + o) = lp;
}

// ---------------- K4 ----------------
__global__ void k4_qk(const float* __restrict__ wq, const float* __restrict__ wk)
{
    __shared__ float sw[64];
    int tid = threadIdx.x;
    if (tid < 64) sw[tid] = (tid < 32) ? wq[tid] : wk[tid - 32];
    __syncthreads();
    size_t g = (size_t)blockIdx.x * 256 + tid;
    const float4* xr = (const float4*)(g_xta + g * FI);
    float aq = 0.f, ak = 0.f;
#pragma unroll
    for (int u = 0; u < 8; u++) {
        float4 v = xr[u];
        aq += v.x*sw[u*4+0] + v.y*sw[u*4+1] + v.z*sw[u*4+2] + v.w*sw[u*4+3];
        ak += v.x*sw[32+u*4+0] + v.y*sw[32+u*4+1] + v.z*sw[32+u*4+2] + v.w*sw[32+u*4+3];
    }
    int n = (int)(g % NN);
    size_t bt = g / NN;
    int t = (int)(bt % T);
    int b = (int)(bt / T);
    size_t o = ((size_t)b*NN + n) * T + t;
    g_qs[o] = aq; g_ks[o] = ak;
}

// ---------------- K5: spatial attention + fused cheb-mul + fast bf16 split ----------------
// hi = bit-truncated bf16 (PRMT packs 2/instr); lo = rn-rounded residual (exact subtract).
__global__ __launch_bounds__(256) void k5_sa(const float* __restrict__ cheb)
{
    __shared__ float buf[NN];
    __shared__ float red[256];
    __shared__ float qr[T];
    int b = blockIdx.x >> 11;
    int i = blockIdx.x & (NN - 1);
    int tid = threadIdx.x;
    const float* qsb = g_qs + ((size_t)b*NN + i) * T;
    const float* ksb = g_ks + (size_t)b*NN*T;
    if (tid < T) qr[tid] = qsb[tid];
    __syncthreads();
    const float isT = 0.28867513459481287f;
    float lmax = -1e30f;
    for (int m = tid; m < NN; m += 256) {
        const float4* kr = (const float4*)(ksb + (size_t)m * T);
        float4 A = kr[0], Bv = kr[1], C = kr[2];
        float s = qr[0]*A.x + qr[1]*A.y + qr[2]*A.z + qr[3]*A.w
                + qr[4]*Bv.x + qr[5]*Bv.y + qr[6]*Bv.z + qr[7]*Bv.w
                + qr[8]*C.x + qr[9]*C.y + qr[10]*C.z + qr[11]*C.w;
        s *= isT;
        buf[m] = s;
        lmax = fmaxf(lmax, s);
    }
    red[tid] = lmax; __syncthreads();
    for (int s = 128; s > 0; s >>= 1) { if (tid < s) red[tid] = fmaxf(red[tid], red[tid+s]); __syncthreads(); }
    float mx = red[0]; __syncthreads();
    float lsum = 0.f;
    for (int m = tid; m < NN; m += 256) { float e = __expf(buf[m]-mx); buf[m] = e; lsum += e; }
    red[tid] = lsum; __syncthreads();
    for (int s = 128; s > 0; s >>= 1) { if (tid < s) red[tid] += red[tid+s]; __syncthreads(); }
    float inv = 1.f / red[0];
    // prescale softmax row by inv (shared across the 3 k's)
    for (int m = tid; m < NN; m += 256) buf[m] *= inv;
    __syncthreads();

    const int m0 = tid * 8;
    float4 s0 = *(const float4*)(buf + m0);
    float4 s1 = *(const float4*)(buf + m0 + 4);
    size_t rowoff = (size_t)i * NN + m0;
#pragma unroll
    for (int k = 0; k < 3; k++) {
        const float4* cb = (const float4*)(cheb + (size_t)k*NN*NN + rowoff);
        float4 c0 = cb[0], c1 = cb[1];
        float a0 = c0.x*s0.x, a1 = c0.y*s0.y, a2 = c0.z*s0.z, a3 = c0.w*s0.w;
        float a4 = c1.x*s1.x, a5 = c1.y*s1.y, a6 = c1.z*s1.z, a7 = c1.w*s1.w;
        unsigned u0 = __float_as_uint(a0), u1 = __float_as_uint(a1);
        unsigned u2 = __float_as_uint(a2), u3 = __float_as_uint(a3);
        unsigned u4 = __float_as_uint(a4), u5 = __float_as_uint(a5);
        unsigned u6 = __float_as_uint(a6), u7 = __float_as_uint(a7);
        uint4 hv;
        hv.x = __byte_perm(u0, u1, 0x7632);
        hv.y = __byte_perm(u2, u3, 0x7632);
        hv.z = __byte_perm(u4, u5, 0x7632);
        hv.w = __byte_perm(u6, u7, 0x7632);
        float l0 = a0 - __uint_as_float(u0 & 0xFFFF0000u);
        float l1 = a1 - __uint_as_float(u1 & 0xFFFF0000u);
        float l2 = a2 - __uint_as_float(u2 & 0xFFFF0000u);
        float l3 = a3 - __uint_as_float(u3 & 0xFFFF0000u);
        float l4 = a4 - __uint_as_float(u4 & 0xFFFF0000u);
        float l5 = a5 - __uint_as_float(u5 & 0xFFFF0000u);
        float l6 = a6 - __uint_as_float(u6 & 0xFFFF0000u);
        float l7 = a7 - __uint_as_float(u7 & 0xFFFF0000u);
        uint4 lv;
        lv.x = bf2(l1, l0);
        lv.y = bf2(l3, l2);
        lv.z = bf2(l5, l4);
        lv.w = bf2(l7, l6);
        size_t o = ((size_t)(k*B + b)*NN + i)*NN + m0;
        *(uint4*)(g_ah + o) = hv;
        *(uint4*)(g_al + o) = lv;
    }
}

// ---------------- K6: 16m x 384n x 2048k bf16-split MMA; A read once chip-wide ----------
#define ST_BYTES 110592
#define K6_SMEM  221184

__device__ __forceinline__ void k6_issue(int tid, uint32_t sb, int s, int b, int i0, int j0)
{
    uint32_t base = sb + (uint32_t)s * ST_BYTES;
#pragma unroll
    for (int r = 0; r < 14; r++) {
        int idx = tid + 512*r;
        if (idx < 768) {
            int k = idx >> 8, rem = idx & 255;
            int half = rem >> 7, rr = (rem >> 3) & 15, c = rem & 7;
            const unsigned short* src = (half ? g_al : g_ah)
                + (((size_t)(k*B + b)*NN + (i0 + rr))*NN + j0 + c*8);
            cp16(base + k*4096 + half*2048 + SWZ((uint32_t)(rr*128 + c*16)), src);
        } else if (idx < 6912) {
            int bi = idx - 768;
            int rr = bi >> 4, half = (bi >> 3) & 1, c = bi & 7;
            const unsigned short* src = (half ? g_xbl : g_xbh)
                + ((size_t)b*(T*FI) + rr)*NN + j0 + c*8;
            cp16(base + 12288 + half*49152 + SWZ((uint32_t)(rr*128 + c*16)), src);
        }
    }
}

__global__ __launch_bounds__(512, 1)
void k6_mma(const float* __restrict__ theta)
{
    extern __shared__ __align__(1024) char smem[];
    const int b  = blockIdx.y;
    const int i0 = blockIdx.x << 4;
    const int tid = threadIdx.x, wid = tid >> 5, lane = tid & 31;
    const int g = lane >> 2, q = lane & 3;
    const int wn = wid;
    const uint32_t sb = s2u(smem);

    const uint32_t aRow  = (uint32_t)((((lane >> 3) & 1)*8 + (lane & 7))*128 + (lane >> 4)*16);
    const uint32_t bRow4 = (uint32_t)((wn*24 + ((lane >> 4) & 1)*8 + (lane & 7))*128
                                      + ((lane >> 3) & 1)*16);
    const uint32_t bRow2 = (uint32_t)((wn*24 + 16 + (lane & 7))*128 + ((lane >> 3) & 1)*16);

    float acc[3][3][4];
#pragma unroll
    for (int k = 0; k < 3; k++)
#pragma unroll
        for (int nt = 0; nt < 3; nt++)
#pragma unroll
            for (int c = 0; c < 4; c++) acc[k][nt][c] = 0.f;

    k6_issue(tid, sb, 0, b, i0, 0);
    CP_COMMIT();

    for (int it = 0; it < 32; it++) {
        const int cur = it & 1;
        if (it + 1 < 32) {
            k6_issue(tid, sb, cur ^ 1, b, i0, (it + 1) * 64);
            CP_COMMIT();
            asm volatile("cp.async.wait_group 1;" ::: "memory");
        } else {
            asm volatile("cp.async.wait_group 0;" ::: "memory");
        }
        __syncthreads();

        const uint32_t A0  = sb + (uint32_t)cur * ST_BYTES;
        const uint32_t Bhi = A0 + 12288;
        const uint32_t Blo = Bhi + 49152;
#pragma unroll
        for (int kk = 0; kk < 4; kk++) {
            const uint32_t kb = (uint32_t)kk * 32;
            unsigned bh[6], bl[6];
            ldsm4(bh[0], bh[1], bh[2], bh[3], Bhi + SWZ(bRow4 + kb));
            ldsm2(bh[4], bh[5],               Bhi + SWZ(bRow2 + kb));
            ldsm4(bl[0], bl[1], bl[2], bl[3], Blo + SWZ(bRow4 + kb));
            ldsm2(bl[4], bl[5],               Blo + SWZ(bRow2 + kb));
#pragma unroll
            for (int k = 0; k < 3; k++) {
                const uint32_t Ak = A0 + (uint32_t)k * 4096;
                unsigned ah[4], al[4];
                ldsm4(ah[0], ah[1], ah[2], ah[3], Ak + SWZ(aRow + kb));
                ldsm4(al[0], al[1], al[2], al[3], Ak + 2048 + SWZ(aRow + kb));
                mma_bf16(acc[k][0], ah, bh + 0);
                mma_bf16(acc[k][1], ah, bh + 2);
                mma_bf16(acc[k][2], ah, bh + 4);
                mma_bf16(acc[k][0], ah, bl + 0);
                mma_bf16(acc[k][1], ah, bl + 2);
                mma_bf16(acc[k][2], ah, bl + 4);
                mma_bf16(acc[k][0], al, bh + 0);
                mma_bf16(acc[k][1], al, bh + 2);
                mma_bf16(acc[k][2], al, bh + 4);
            }
        }
        __syncthreads();
    }

    // ---- epilogue: theta contraction + relu, write g_xgc ----
    float* Cs  = (float*)smem;                  // [16][392]
    float* ths = (float*)(smem + 25600);        // [3][32][64]
    for (int idx = tid; idx < KC*FI*FO; idx += 512) ths[idx] = theta[idx];

    const int row = tid >> 5;
    const int op  = (tid & 31) * 2;

    float out[T][2];
#pragma unroll
    for (int t = 0; t < T; t++) { out[t][0] = 0.f; out[t][1] = 0.f; }

#pragma unroll
    for (int k = 0; k < 3; k++) {
        __syncthreads();
#pragma unroll
        for (int nt = 0; nt < 3; nt++) {
            int col = wn*24 + nt*8 + q*2;
            Cs[g*392 + col]     = acc[k][nt][0];
            Cs[g*392 + col + 1] = acc[k][nt][1];
            Cs[(g+8)*392 + col]     = acc[k][nt][2];
            Cs[(g+8)*392 + col + 1] = acc[k][nt][3];
        }
        __syncthreads();
        const float* cr = Cs + row*392;
#pragma unroll
        for (int f = 0; f < FI; f++) {
            float2 tv = *(const float2*)(ths + (k*FI + f)*FO + op);
#pragma unroll
            for (int t = 0; t < T; t++) {
                float cv = cr[t*32 + f];
                out[t][0] += cv * tv.x;
                out[t][1] += cv * tv.y;
            }
        }
    }
#pragma unroll
    for (int t = 0; t < T; t++) {
        float2 v;
        v.x = fmaxf(out[t][0], 0.f);
        v.y = fmaxf(out[t][1], 0.f);
        *(float2*)(g_xgc + (((size_t)b*T + t)*NN + i0 + row)*FO + op) = v;
    }
}

// ---------------- K7 ----------------
#define S7_WS   0
#define S7_XG   15232
#define S7_XR   (S7_XG + 6144)
#define S7_YB   (S7_XR + 1024)
#define S7_MU   (S7_YB + 2080)
#define S7_RI   (S7_MU + 32)
#define S7_TOTF (S7_RI + 32)

__global__ __launch_bounds__(256) void k7_final(
    const float* __restrict__ x,
    const float* __restrict__ tw, const float* __restrict__ tb,
    const float* __restrict__ rw, const float* __restrict__ rb,
    const float* __restrict__ lg, const float* __restrict__ lb,
    float* __restrict__ out)
{
    extern __shared__ float s7[];
    float* Ws = s7 + S7_WS;
    float* xg = s7 + S7_XG;
    float* xr = s7 + S7_XR;
    float* yb = s7 + S7_YB;
    float* mu = s7 + S7_MU;
    float* ri = s7 + S7_RI;

    int b = blockIdx.z, t = blockIdx.y, n0 = blockIdx.x << 5;
    int tid = threadIdx.x;

    for (int idx = tid; idx < FO*192; idx += 256) { int o = idx / 192, r = idx - o*192; Ws[r*68 + o] = tw[idx]; }
    for (int idx = tid; idx < FO*FI; idx += 256) { int o = idx >> 5, f = idx & 31; Ws[(192+f)*68 + o] = rw[idx]; }
#pragma unroll
    for (int dt = 0; dt < 3; dt++) {
        int ts = t + dt - 1;
        if (ts >= 0 && ts < T) {
            const float* src = g_xgc + (((size_t)b*T + ts)*NN + n0) * FO;
            for (int idx = tid; idx < 32*FO; idx += 256) xg[dt*2048 + idx] = src[idx];
        } else {
            for (int idx = tid; idx < 32*FO; idx += 256) xg[dt*2048 + idx] = 0.f;
        }
    }
    {
        const float* src = x + (((size_t)b*T + t)*NN + n0) * FI;
        for (int idx = tid; idx < 32*FI; idx += 256) xr[idx] = src[idx];
    }
    __syncthreads();

    int og = tid & 15, nlg = tid >> 4;
    int o0 = og << 2, nl0 = nlg << 1;
    float4 tb4 = *(const float4*)(tb + o0);
    float4 rb4 = *(const float4*)(rb + o0);
    float acc0[4], acc1[4];
#pragma unroll
    for (int c = 0; c < 4; c++) {
        float bia = ((const float*)&tb4)[c] + ((const float*)&rb4)[c];
        acc0[c] = bia; acc1[c] = bia;
    }

    for (int c = 0; c < FO; c++) {
#pragma unroll
        for (int dt = 0; dt < 3; dt++) {
            float4 w = *(const float4*)(Ws + (c*3 + dt)*68 + o0);
            float xa = xg[dt*2048 + nl0*FO + c];
            float xb2 = xg[dt*2048 + nl0*FO + FO + c];
            acc0[0] += xa*w.x;  acc0[1] += xa*w.y;  acc0[2] += xa*w.z;  acc0[3] += xa*w.w;
            acc1[0] += xb2*w.x; acc1[1] += xb2*w.y; acc1[2] += xb2*w.z; acc1[3] += xb2*w.w;
        }
    }
#pragma unroll
    for (int f = 0; f < FI; f++) {
        float4 w = *(const float4*)(Ws + (192 + f)*68 + o0);
        float xa = xr[nl0*FI + f];
        float xb2 = xr[nl0*FI + FI + f];
        acc0[0] += xa*w.x;  acc0[1] += xa*w.y;  acc0[2] += xa*w.z;  acc0[3] += xa*w.w;
        acc1[0] += xb2*w.x; acc1[1] += xb2*w.y; acc1[2] += xb2*w.z; acc1[3] += xb2*w.w;
    }
#pragma unroll
    for (int c = 0; c < 4; c++) {
        yb[nl0*65 + o0 + c]     = acc0[c] > 0.f ? acc0[c] : 0.f;
        yb[(nl0+1)*65 + o0 + c] = acc1[c] > 0.f ? acc1[c] : 0.f;
    }
    __syncthreads();
    if (tid < 32) {
        float m = 0.f;
#pragma unroll
        for (int o = 0; o < FO; o++) m += yb[tid*65 + o];
        m *= (1.f/FO);
        float v = 0.f;
#pragma unroll
        for (int o = 0; o < FO; o++) { float d = yb[tid*65 + o] - m; v += d*d; }
        v *= (1.f/FO);
        mu[tid] = m;
        ri[tid] = rsqrtf(v + 1e-5f);
    }
    __syncthreads();
    float4 g4 = *(const float4*)(lg + o0);
    float4 b4 = *(const float4*)(lb + o0);
#pragma unroll
    for (int j = 0; j < 2; j++) {
        int nl = nl0 + j;
        float m = mu[nl], r = ri[nl];
        float4 ov;
        ov.x = (yb[nl*65 + o0 + 0] - m)*r*g4.x + b4.x;
        ov.y = (yb[nl*65 + o0 + 1] - m)*r*g4.y + b4.y;
        ov.z = (yb[nl*65 + o0 + 2] - m)*r*g4.z + b4.z;
        ov.w = (yb[nl*65 + o0 + 3] - m)*r*g4.w + b4.w;
        *(float4*)(out + ((((size_t)b*T + t)*NN + n0 + nl) << 6) + o0) = ov;
    }
}

// ---------------- launch ----------------
extern "C" void kernel_launch(void* const* d_in, const int* in_sizes, int n_in,
                              void* d_out, int out_size)
{
    const float* x     = (const float*)d_in[0];
    const float* cheb  = (const float*)d_in[1];
    const float* wq_t  = (const float*)d_in[2];
    const float* wk_t  = (const float*)d_in[3];
    const float* wq_s  = (const float*)d_in[4];
    const float* wk_s  = (const float*)d_in[5];
    const float* theta = (const float*)d_in[6];
    const float* tw    = (const float*)d_in[7];
    const float* tbv   = (const float*)d_in[8];
    const float* rw    = (const float*)d_in[9];
    const float* rbv   = (const float*)d_in[10];
    const float* lg    = (const float*)d_in[11];
    const float* lb    = (const float*)d_in[12];
    float* out = (float*)d_out;

    cudaFuncSetAttribute(k6_mma, cudaFuncAttributeMaxDynamicSharedMemorySize, K6_SMEM);
    cudaFuncSetAttribute(k7_final, cudaFuncAttributeMaxDynamicSharedMemorySize,
                         S7_TOTF * (int)sizeof(float));

    k1_qk<<<(B*T*NN)/256, 256>>>(x, wq_t, wk_t);
    k2_ta<<<B*T, 256>>>();
    k3_xta<<<dim3(NN/32, B), 1024>>>(x);
    k3b_cvt<<<dim3(NN/32, T, B), 256>>>();
    k4_qk<<<(B*T*NN)/256, 256>>>(wq_s, wk_s);
    k5_sa<<<B*NN, 256>>>(cheb);
    k6_mma<<<dim3(NN/16, B), 512, K6_SMEM>>>(theta);
    k7_final<<<dim3(NN/32, T, B), 256, S7_TOTF * (int)sizeof(float)>>>(
        x, tw, tbv, rw, rbv, lg, lb, out);
}